// round 11
// baseline (speedup 1.0000x reference)
#include <cuda_runtime.h>
#include <math.h>

// Problem dims
#define SS 512
#define BB 64
#define II 512
#define HH 1024
#define BH (BB*HH)

// Recurrent decomposition: 8 n-tiles (128 cols) x 16 k-chunks (64 k) = 128 blocks
// Two independent half-batch streams (b 0..31 and 32..63), pipelined.
#define NT 8
#define KC 16
#define NB (NT*KC)
#define HB 32            // half-batch
#define HBH (HB*HH)      // 32768 floats per half-batch step
#define ASP2 36          // As pitch: 32 b + 4 pad

// -------------------- device scratch --------------------------------------------
__device__ float g_pre[SS*BH];          // V x_t + b_V + b_W
__device__ float g_part0[KC][HBH];      // stream-0 split-K partials (2 MB)
__device__ float g_part1[KC][HBH];      // stream-1 split-K partials (2 MB)
__device__ float g_hT0[HH*HB];          // stream-0 transposed h: hT[c][b]
__device__ float g_hT1[HH*HB];          // stream-1 transposed h
__device__ unsigned g_s[256];           // 4 barriers x (cnt,gen), 128B-strided
__device__ unsigned g_bar_cnt = 0;
__device__ volatile unsigned g_bar_gen = 0;

#define CNT_A0 (&g_s[0])
#define GEN_A0 (&g_s[32])
#define CNT_A1 (&g_s[64])
#define GEN_A1 (&g_s[96])
#define CNT_B0 (&g_s[128])
#define GEN_B0 (&g_s[160])
#define CNT_B1 (&g_s[192])
#define GEN_B1 (&g_s[224])

// -------------------- packed f32x2 helpers --------------------------------------
typedef unsigned long long u64;

__device__ __forceinline__ u64 pack2s(float x) {
    u64 r; asm("mov.b64 %0, {%1, %1};" : "=l"(r) : "f"(x)); return r;
}
__device__ __forceinline__ u64 fma2(u64 a, u64 b, u64 c) {
    u64 d; asm("fma.rn.f32x2 %0, %1, %2, %3;" : "=l"(d) : "l"(a), "l"(b), "l"(c));
    return d;
}
__device__ __forceinline__ float2 unpack2(u64 v) {
    float2 f; asm("mov.b64 {%0, %1}, %2;" : "=f"(f.x), "=f"(f.y) : "l"(v)); return f;
}
__device__ __forceinline__ float tanh_fast(float x) {
    float y; asm("tanh.approx.f32 %0, %1;" : "=f"(y) : "f"(x)); return y;
}
__device__ __forceinline__ void st_rlx(unsigned* p, unsigned v) {
    asm volatile("st.relaxed.gpu.global.b32 [%0], %1;" :: "l"(p), "r"(v) : "memory");
}
__device__ __forceinline__ unsigned ld_rlx(const unsigned* p) {
    unsigned v;
    asm volatile("ld.relaxed.gpu.global.b32 %0, [%1];" : "=r"(v) : "l"(p) : "memory");
    return v;
}

// Split arrive/wait ticket barrier. Arrivals of step s+1 cannot begin until the
// release of step s is observed grid-wide (proven by the wait ordering in the
// main loop), so cnt reuse with in-place reset is safe.
__device__ __forceinline__ void bar_arrive(unsigned* cnt, unsigned* gen,
                                           unsigned next, int t) {
    __syncthreads();                 // all threads' prior STGs issued
    if (t == 0) {
        __threadfence();             // publish block's writes before arrival
        if (atomicAdd(cnt, 1u) == NB - 1u) {
            st_rlx(cnt, 0u);
            __threadfence();
            st_rlx(gen, next);       // release
        }
    }
}
__device__ __forceinline__ void bar_wait(unsigned* gen, unsigned v, int t) {
    if (t == 0) {
        while ((int)ld_rlx(gen) < (int)v) { }
        __threadfence();             // acquire
    }
    __syncthreads();
}

// one-time startup grid barrier (volatile ticket, proven replay-safe)
__device__ __forceinline__ void grid_sync_once() {
    __syncthreads();
    __threadfence();
    if (threadIdx.x == 0) {
        unsigned gen = g_bar_gen;
        if (atomicAdd(&g_bar_cnt, 1u) == NB - 1u) {
            g_bar_cnt = 0;
            __threadfence();
            g_bar_gen = gen + 1u;
        } else {
            while (g_bar_gen == gen) { }
        }
    }
    __syncthreads();
}

// =================================================================================
// Kernel 1: g_pre = x @ Vw^T + Vb + Wb  (R9/R10 conflict-free version, proven)
// =================================================================================
__global__ void __launch_bounds__(256) pre_gemm_kernel(
        const float* __restrict__ x,
        const float* __restrict__ Vw,
        const float* __restrict__ Wb,
        const float* __restrict__ Vb) {
    __shared__ float As[128][20];
    __shared__ float Ws[16][132];

    const int bm = blockIdx.x;
    const int bn = blockIdx.y;
    const int t  = threadIdx.x;
    const int tx = t & 15;
    const int ty = t >> 4;

    u64 acc[8][4];
    #pragma unroll
    for (int j = 0; j < 8; j++)
        #pragma unroll
        for (int p = 0; p < 4; p++) acc[j][p] = 0ull;

    const float* Arow = x  + (size_t)(bm*128) * II;
    const float* Wrow = Vw + (size_t)(bn*128) * II;

    for (int kb = 0; kb < II; kb += 16) {
        #pragma unroll
        for (int it = 0; it < 2; it++) {
            int q  = t + it*256;
            int r  = q >> 2;
            int k4 = (q & 3) << 2;
            float4 va = *(const float4*)(Arow + (size_t)r*II + kb + k4);
            *(float4*)&As[r][k4] = va;
            float4 vw = *(const float4*)(Wrow + (size_t)r*II + kb + k4);
            Ws[k4+0][r] = vw.x; Ws[k4+1][r] = vw.y;
            Ws[k4+2][r] = vw.z; Ws[k4+3][r] = vw.w;
        }
        __syncthreads();
        #pragma unroll
        for (int k = 0; k < 16; k++) {
            ulonglong2 w01 = *(const ulonglong2*)&Ws[k][tx*4];
            ulonglong2 w23 = *(const ulonglong2*)&Ws[k][tx*4 + 64];
            #pragma unroll
            for (int j = 0; j < 8; j++) {
                u64 ap = pack2s(As[ty*8 + j][k]);
                acc[j][0] = fma2(ap, w01.x, acc[j][0]);
                acc[j][1] = fma2(ap, w01.y, acc[j][1]);
                acc[j][2] = fma2(ap, w23.x, acc[j][2]);
                acc[j][3] = fma2(ap, w23.y, acc[j][3]);
            }
        }
        __syncthreads();
    }

    const int nb0 = bn*128 + tx*4;
    const int nb1 = nb0 + 64;
    float b0[4], b1[4];
    #pragma unroll
    for (int i = 0; i < 4; i++) {
        b0[i] = Vb[nb0+i] + Wb[nb0+i];
        b1[i] = Vb[nb1+i] + Wb[nb1+i];
    }

    #pragma unroll
    for (int j = 0; j < 8; j++) {
        size_t row = (size_t)bm*128 + ty*8 + j;
        float2 c0 = unpack2(acc[j][0]);
        float2 c1 = unpack2(acc[j][1]);
        float2 c2 = unpack2(acc[j][2]);
        float2 c3 = unpack2(acc[j][3]);
        float4 o0 = make_float4(c0.x+b0[0], c0.y+b0[1], c1.x+b0[2], c1.y+b0[3]);
        float4 o1 = make_float4(c2.x+b1[0], c2.y+b1[1], c3.x+b1[2], c3.y+b1[3]);
        *(float4*)&g_pre[row*HH + nb0] = o0;
        *(float4*)&g_pre[row*HH + nb1] = o1;
    }
}

// =================================================================================
// Kernel 2: persistent recurrence, dual-stream pipelined.
//   Per block (nt,kc): A-phase tile b=32, n=128, k=64 per stream (4b x 8n micro,
//   conflict-free w, broadcast a). B-phase: one float2 per thread per stream.
//   Order per step: W(B0) A0 Arr(A0) W(B1) A1 Arr(A1) W(A0) B0 Arr(B0) W(A1) B1 Arr(B1)
//   Every wait hides behind ~1us of the other stream's work.
// =================================================================================
__global__ void __launch_bounds__(128) rnn_recurrent_kernel(
        const float* __restrict__ Ww,
        float* __restrict__ out) {
    extern __shared__ float smem[];
    float* Ws  = smem;                    // [k=64][n=128]  32 KB
    float* As0 = smem + 64*128;           // [k=64][ASP2]   9.2 KB
    float* As1 = As0 + 64*ASP2;           // [k=64][ASP2]   9.2 KB

    const int bid = blockIdx.x;
    const int nt  = bid & (NT-1);
    const int kc  = bid >> 3;
    const int t   = threadIdx.x;
    const int tx  = t & 15;               // n group (cols tx*4, 64+tx*4)
    const int ty  = t >> 4;               // b group (rows ty*4..+3, 8 groups x 4 = 32)

    if (bid == 0) { g_s[t] = 0; g_s[t+128] = 0; }

    // Resident Ww slice transposed: Ws[k][n] = Ww[nt*128+n][kc*64+k]
    for (int q = t; q < 128*16; q += 128) {
        int n  = q >> 4;
        int k4 = (q & 15) << 2;
        float4 v = *(const float4*)(Ww + (size_t)(nt*128 + n)*HH + kc*64 + k4);
        Ws[(k4+0)*128 + n] = v.x;
        Ws[(k4+1)*128 + n] = v.y;
        Ws[(k4+2)*128 + n] = v.z;
        Ws[(k4+3)*128 + n] = v.w;
    }
    grid_sync_once();   // publishes zeroed sync words

    // B-role: one float2 per thread per stream over half-batch slab
    const int o2 = (bid*128 + t)*2;       // 0..32766, covers HBH
    const int hb = o2 >> 10;              // local batch row 0..31
    const int hc = o2 & 1023;             // hidden col (even)

    float2 hlast0, hlast1;

    // ---- step 0: h_0 = tanh(pre_0), both streams ----
    {
        float2 p0 = *(const float2*)&g_pre[(size_t)hb*HH + hc];
        float2 h0 = make_float2(tanh_fast(p0.x), tanh_fast(p0.y));
        *(float2*)&out[(size_t)hb*HH + hc] = h0;
        g_hT0[(hc+0)*HB + hb] = h0.x;
        g_hT0[(hc+1)*HB + hb] = h0.y;
        hlast0 = h0;

        float2 p1 = *(const float2*)&g_pre[(size_t)(hb+HB)*HH + hc];
        float2 h1 = make_float2(tanh_fast(p1.x), tanh_fast(p1.y));
        *(float2*)&out[(size_t)(hb+HB)*HH + hc] = h1;
        g_hT1[(hc+0)*HB + hb] = h1.x;
        g_hT1[(hc+1)*HB + hb] = h1.y;
        hlast1 = h1;
    }
    bar_arrive(CNT_B0, GEN_B0, 1u, t);
    bar_arrive(CNT_B1, GEN_B1, 1u, t);

    for (int s = 1; s < SS; s++) {
        const unsigned us = (unsigned)s;

        // ================= stream 0: A phase =================
        bar_wait(GEN_B0, us, t);          // hT0(s-1) visible; partials0 WAR clear
        {
            const float* src = &g_hT0[kc*64*HB];
            #pragma unroll
            for (int j = 0; j < 4; j++) {
                int off4 = t + j*128;             // 512 float4s = 64k x 32b
                int kk   = off4 >> 3;
                int b4   = (off4 & 7) << 2;
                float4 v = __ldcg((const float4*)(src + off4*4));
                *(float4*)&As0[kk*ASP2 + b4] = v;
            }
        }
        __syncthreads();
        {
            u64 acc[4][4];
            #pragma unroll
            for (int j = 0; j < 4; j++)
                #pragma unroll
                for (int p = 0; p < 4; p++) acc[j][p] = 0ull;
            #pragma unroll 8
            for (int k = 0; k < 64; k++) {
                float4 a4 = *(const float4*)&As0[k*ASP2 + ty*4];
                const float* wr = Ws + k*128 + tx*4;
                ulonglong2 w01 = *(const ulonglong2*)(wr);
                ulonglong2 w23 = *(const ulonglong2*)(wr + 64);
                u64 a;
                a = pack2s(a4.x);
                acc[0][0] = fma2(a, w01.x, acc[0][0]);
                acc[0][1] = fma2(a, w01.y, acc[0][1]);
                acc[0][2] = fma2(a, w23.x, acc[0][2]);
                acc[0][3] = fma2(a, w23.y, acc[0][3]);
                a = pack2s(a4.y);
                acc[1][0] = fma2(a, w01.x, acc[1][0]);
                acc[1][1] = fma2(a, w01.y, acc[1][1]);
                acc[1][2] = fma2(a, w23.x, acc[1][2]);
                acc[1][3] = fma2(a, w23.y, acc[1][3]);
                a = pack2s(a4.z);
                acc[2][0] = fma2(a, w01.x, acc[2][0]);
                acc[2][1] = fma2(a, w01.y, acc[2][1]);
                acc[2][2] = fma2(a, w23.x, acc[2][2]);
                acc[2][3] = fma2(a, w23.y, acc[2][3]);
                a = pack2s(a4.w);
                acc[3][0] = fma2(a, w01.x, acc[3][0]);
                acc[3][1] = fma2(a, w01.y, acc[3][1]);
                acc[3][2] = fma2(a, w23.x, acc[3][2]);
                acc[3][3] = fma2(a, w23.y, acc[3][3]);
            }
            #pragma unroll
            for (int j = 0; j < 4; j++) {
                float* dst = &g_part0[kc][(size_t)(ty*4 + j)*HH + nt*128 + tx*4];
                ulonglong2 v0; v0.x = acc[j][0]; v0.y = acc[j][1];
                ulonglong2 v1; v1.x = acc[j][2]; v1.y = acc[j][3];
                *(ulonglong2*)(dst)      = v0;
                *(ulonglong2*)(dst + 64) = v1;
            }
        }
        bar_arrive(CNT_A0, GEN_A0, us, t);

        // ================= stream 1: A phase =================
        bar_wait(GEN_B1, us, t);
        {
            const float* src = &g_hT1[kc*64*HB];
            #pragma unroll
            for (int j = 0; j < 4; j++) {
                int off4 = t + j*128;
                int kk   = off4 >> 3;
                int b4   = (off4 & 7) << 2;
                float4 v = __ldcg((const float4*)(src + off4*4));
                *(float4*)&As1[kk*ASP2 + b4] = v;
            }
        }
        __syncthreads();
        {
            u64 acc[4][4];
            #pragma unroll
            for (int j = 0; j < 4; j++)
                #pragma unroll
                for (int p = 0; p < 4; p++) acc[j][p] = 0ull;
            #pragma unroll 8
            for (int k = 0; k < 64; k++) {
                float4 a4 = *(const float4*)&As1[k*ASP2 + ty*4];
                const float* wr = Ws + k*128 + tx*4;
                ulonglong2 w01 = *(const ulonglong2*)(wr);
                ulonglong2 w23 = *(const ulonglong2*)(wr + 64);
                u64 a;
                a = pack2s(a4.x);
                acc[0][0] = fma2(a, w01.x, acc[0][0]);
                acc[0][1] = fma2(a, w01.y, acc[0][1]);
                acc[0][2] = fma2(a, w23.x, acc[0][2]);
                acc[0][3] = fma2(a, w23.y, acc[0][3]);
                a = pack2s(a4.y);
                acc[1][0] = fma2(a, w01.x, acc[1][0]);
                acc[1][1] = fma2(a, w01.y, acc[1][1]);
                acc[1][2] = fma2(a, w23.x, acc[1][2]);
                acc[1][3] = fma2(a, w23.y, acc[1][3]);
                a = pack2s(a4.z);
                acc[2][0] = fma2(a, w01.x, acc[2][0]);
                acc[2][1] = fma2(a, w01.y, acc[2][1]);
                acc[2][2] = fma2(a, w23.x, acc[2][2]);
                acc[2][3] = fma2(a, w23.y, acc[2][3]);
                a = pack2s(a4.w);
                acc[3][0] = fma2(a, w01.x, acc[3][0]);
                acc[3][1] = fma2(a, w01.y, acc[3][1]);
                acc[3][2] = fma2(a, w23.x, acc[3][2]);
                acc[3][3] = fma2(a, w23.y, acc[3][3]);
            }
            #pragma unroll
            for (int j = 0; j < 4; j++) {
                float* dst = &g_part1[kc][(size_t)(ty*4 + j)*HH + nt*128 + tx*4];
                ulonglong2 v0; v0.x = acc[j][0]; v0.y = acc[j][1];
                ulonglong2 v1; v1.x = acc[j][2]; v1.y = acc[j][3];
                *(ulonglong2*)(dst)      = v0;
                *(ulonglong2*)(dst + 64) = v1;
            }
        }
        bar_arrive(CNT_A1, GEN_A1, us, t);

        // prefetch pre for both B phases (independent of partials)
        float2 pre0 = *(const float2*)&g_pre[(size_t)s*BH + (size_t)hb*HH + hc];
        float2 pre1 = *(const float2*)&g_pre[(size_t)s*BH + (size_t)(hb+HB)*HH + hc];

        // ================= stream 0: B phase =================
        bar_wait(GEN_A0, us, t);
        {
            float2 a2 = pre0;
            #pragma unroll
            for (int kk = 0; kk < KC; kk++) {
                float2 p = __ldcg((const float2*)&g_part0[kk][o2]);
                a2.x += p.x; a2.y += p.y;
            }
            float2 h = make_float2(tanh_fast(a2.x), tanh_fast(a2.y));
            *(float2*)&out[(size_t)s*BH + (size_t)hb*HH + hc] = h;
            g_hT0[(hc+0)*HB + hb] = h.x;
            g_hT0[(hc+1)*HB + hb] = h.y;
            hlast0 = h;
        }
        bar_arrive(CNT_B0, GEN_B0, us + 1u, t);

        // ================= stream 1: B phase =================
        bar_wait(GEN_A1, us, t);
        {
            float2 a2 = pre1;
            #pragma unroll
            for (int kk = 0; kk < KC; kk++) {
                float2 p = __ldcg((const float2*)&g_part1[kk][o2]);
                a2.x += p.x; a2.y += p.y;
            }
            float2 h = make_float2(tanh_fast(a2.x), tanh_fast(a2.y));
            *(float2*)&out[(size_t)s*BH + (size_t)(hb+HB)*HH + hc] = h;
            g_hT1[(hc+0)*HB + hb] = h.x;
            g_hT1[(hc+1)*HB + hb] = h.y;
            hlast1 = h;
        }
        bar_arrive(CNT_B1, GEN_B1, us + 1u, t);
    }

    // h_final: values this thread computed at s=511
    *(float2*)&out[(size_t)SS*BH + (size_t)hb*HH + hc]      = hlast0;
    *(float2*)&out[(size_t)SS*BH + (size_t)(hb+HB)*HH + hc] = hlast1;
}

// =================================================================================
// Launch
// =================================================================================
extern "C" void kernel_launch(void* const* d_in, const int* in_sizes, int n_in,
                              void* d_out, int out_size) {
    const float* x  = (const float*)d_in[0];   // (S,B,I)
    const float* Ww = (const float*)d_in[1];   // (H,H)
    const float* Wb = (const float*)d_in[2];   // (H)
    const float* Vw = (const float*)d_in[3];   // (H,I)
    const float* Vb = (const float*)d_in[4];   // (H)
    float* out = (float*)d_out;                // (S,B,H) then (1,B,H)

    dim3 g1(256, 8);
    pre_gemm_kernel<<<g1, 256>>>(x, Vw, Wb, Vb);

    static int smem_set = 0;
    const int smem_bytes = (64*128 + 2*64*ASP2) * (int)sizeof(float);  // 51200 - adjusted
    if (!smem_set) {
        cudaFuncSetAttribute(rnn_recurrent_kernel,
                             cudaFuncAttributeMaxDynamicSharedMemorySize, smem_bytes);
        smem_set = 1;
    }
    rnn_recurrent_kernel<<<NB, 128, smem_bytes>>>(Ww, out);
}

// round 12
// speedup vs baseline: 1.1240x; 1.1240x over previous
#include <cuda_runtime.h>
#include <math.h>

// Problem dims
#define SS 512
#define BB 64
#define II 512
#define HH 1024
#define BH (BB*HH)

// Recurrent decomposition: 64 clusters = 16 n-tiles(64 cols) x 4 b-groups(16 rows),
// each cluster = 2 blocks splitting K in halves of 512. 128 blocks total.
#define NCL 64
#define KH  512
#define NB  128
#define ASP 20          // As row pitch (16 b + 4 pad)

// -------------------- device scratch --------------------------------------------
__device__ float g_pre[SS*BH];          // V x_t + b_V + b_W
__device__ float g_pp[NCL][16*64];      // per-cluster rank0 partial (16b x 64n)
__device__ float g_hT[2][HH*BB];        // parity transposed h: hT[c][b]
__device__ unsigned g_flag[NCL*32];     // pairwise handoff flags, 128B stride
__device__ unsigned g_bar_cnt = 0;
__device__ volatile unsigned g_bar_gen = 0;

// -------------------- packed f32x2 helpers --------------------------------------
typedef unsigned long long u64;

__device__ __forceinline__ u64 pack2s(float x) {
    u64 r; asm("mov.b64 %0, {%1, %1};" : "=l"(r) : "f"(x)); return r;
}
__device__ __forceinline__ u64 fma2(u64 a, u64 b, u64 c) {
    u64 d; asm("fma.rn.f32x2 %0, %1, %2, %3;" : "=l"(d) : "l"(a), "l"(b), "l"(c));
    return d;
}
__device__ __forceinline__ float2 unpack2(u64 v) {
    float2 f; asm("mov.b64 {%0, %1}, %2;" : "=f"(f.x), "=f"(f.y) : "l"(v)); return f;
}
__device__ __forceinline__ float tanh_fast(float x) {
    float y; asm("tanh.approx.f32 %0, %1;" : "=f"(y) : "f"(x)); return y;
}
__device__ __forceinline__ void st_rlx(unsigned* p, unsigned v) {
    asm volatile("st.relaxed.gpu.global.b32 [%0], %1;" :: "l"(p), "r"(v) : "memory");
}
__device__ __forceinline__ unsigned ld_rlx(const unsigned* p) {
    unsigned v;
    asm volatile("ld.relaxed.gpu.global.b32 %0, [%1];" : "=r"(v) : "l"(p) : "memory");
    return v;
}

// -------------------- global ticket barrier (R2/R10-proven) ----------------------
__device__ __forceinline__ void grid_sync() {
    __syncthreads();
    __threadfence();
    if (threadIdx.x == 0) {
        unsigned gen = g_bar_gen;
        if (atomicAdd(&g_bar_cnt, 1u) == NB - 1u) {
            g_bar_cnt = 0;
            __threadfence();
            g_bar_gen = gen + 1u;
        } else {
            while (g_bar_gen == gen) { }
        }
    }
    __syncthreads();
}

// =================================================================================
// Kernel 1: g_pre = x @ Vw^T + Vb + Wb  (R9/R10 conflict-free version, proven)
// =================================================================================
__global__ void __launch_bounds__(256) pre_gemm_kernel(
        const float* __restrict__ x,
        const float* __restrict__ Vw,
        const float* __restrict__ Wb,
        const float* __restrict__ Vb) {
    __shared__ float As[128][20];
    __shared__ float Ws[16][132];

    const int bm = blockIdx.x;
    const int bn = blockIdx.y;
    const int t  = threadIdx.x;
    const int tx = t & 15;
    const int ty = t >> 4;

    u64 acc[8][4];
    #pragma unroll
    for (int j = 0; j < 8; j++)
        #pragma unroll
        for (int p = 0; p < 4; p++) acc[j][p] = 0ull;

    const float* Arow = x  + (size_t)(bm*128) * II;
    const float* Wrow = Vw + (size_t)(bn*128) * II;

    for (int kb = 0; kb < II; kb += 16) {
        #pragma unroll
        for (int it = 0; it < 2; it++) {
            int q  = t + it*256;
            int r  = q >> 2;
            int k4 = (q & 3) << 2;
            float4 va = *(const float4*)(Arow + (size_t)r*II + kb + k4);
            *(float4*)&As[r][k4] = va;
            float4 vw = *(const float4*)(Wrow + (size_t)r*II + kb + k4);
            Ws[k4+0][r] = vw.x; Ws[k4+1][r] = vw.y;
            Ws[k4+2][r] = vw.z; Ws[k4+3][r] = vw.w;
        }
        __syncthreads();
        #pragma unroll
        for (int k = 0; k < 16; k++) {
            ulonglong2 w01 = *(const ulonglong2*)&Ws[k][tx*4];
            ulonglong2 w23 = *(const ulonglong2*)&Ws[k][tx*4 + 64];
            #pragma unroll
            for (int j = 0; j < 8; j++) {
                u64 ap = pack2s(As[ty*8 + j][k]);
                acc[j][0] = fma2(ap, w01.x, acc[j][0]);
                acc[j][1] = fma2(ap, w01.y, acc[j][1]);
                acc[j][2] = fma2(ap, w23.x, acc[j][2]);
                acc[j][3] = fma2(ap, w23.y, acc[j][3]);
            }
        }
        __syncthreads();
    }

    const int nb0 = bn*128 + tx*4;
    const int nb1 = nb0 + 64;
    float b0[4], b1[4];
    #pragma unroll
    for (int i = 0; i < 4; i++) {
        b0[i] = Vb[nb0+i] + Wb[nb0+i];
        b1[i] = Vb[nb1+i] + Wb[nb1+i];
    }

    #pragma unroll
    for (int j = 0; j < 8; j++) {
        size_t row = (size_t)bm*128 + ty*8 + j;
        float2 c0 = unpack2(acc[j][0]);
        float2 c1 = unpack2(acc[j][1]);
        float2 c2 = unpack2(acc[j][2]);
        float2 c3 = unpack2(acc[j][3]);
        float4 o0 = make_float4(c0.x+b0[0], c0.y+b0[1], c1.x+b0[2], c1.y+b0[3]);
        float4 o1 = make_float4(c2.x+b1[0], c2.y+b1[1], c3.x+b1[2], c3.y+b1[3]);
        *(float4*)&g_pre[row*HH + nb0] = o0;
        *(float4*)&g_pre[row*HH + nb1] = o1;
    }
}

// =================================================================================
// Kernel 2: persistent recurrence, kc=2 split-K, pairwise handoff, ONE barrier/step.
//   Block bid: cl = bid>>1 (nt = cl&15, bg = cl>>4), r = bid&1.
//   Resident Ww slice: rows nt*64..+64, cols r*512..+512 -> Ws[k][n] (128 KB).
//   Per step: both ranks stage h chunk + compute 16b x 64n partial over their half;
//   rank0 ships partial via L2 + flag; rank1 adds, + pre, tanh, writes out + hT.
//   Then one global ticket barrier.
// =================================================================================
__global__ void __launch_bounds__(128) rnn_recurrent_kernel(
        const float* __restrict__ Ww,
        float* __restrict__ out) {
    extern __shared__ float smem[];
    float* Ws = smem;                 // [k=512][n=64]  128 KB
    float* As = smem + KH*64;         // [k=512][ASP]    40 KB

    const int bid = blockIdx.x;
    const int r   = bid & 1;
    const int cl  = bid >> 1;
    const int nt  = cl & 15;
    const int bg  = cl >> 4;
    const int t   = threadIdx.x;
    const int tx  = t & 15;           // n group: cols tx*4..+3 of 64
    const int ty  = t >> 4;           // b group: rows ty*2, ty*2+1 of 16

    // Resident Ww slice transposed: Ws[k][n] = Ww[nt*64+n][r*512+k]
    for (int q = t; q < 64*128; q += 128) {
        int n  = q >> 7;                  // 0..63
        int k4 = (q & 127) << 2;          // 0..508
        float4 v = *(const float4*)(Ww + (size_t)(nt*64 + n)*HH + r*KH + k4);
        Ws[(k4+0)*64 + n] = v.x;
        Ws[(k4+1)*64 + n] = v.y;
        Ws[(k4+2)*64 + n] = v.z;
        Ws[(k4+3)*64 + n] = v.w;
    }

    const int row0 = bg*16 + ty*2;        // global batch row (first of pair)
    const int col  = nt*64 + tx*4;        // global hidden col (4 consecutive)

    float4 hlast0, hlast1;

    // ---- step 0: h_0 = tanh(pre_0) (rank1 produces its cluster tile) ----
    if (r == 1) {
        float4 p0 = *(const float4*)&g_pre[(size_t)row0*HH + col];
        float4 p1 = *(const float4*)&g_pre[(size_t)(row0+1)*HH + col];
        float4 h0 = make_float4(tanh_fast(p0.x), tanh_fast(p0.y),
                                tanh_fast(p0.z), tanh_fast(p0.w));
        float4 h1 = make_float4(tanh_fast(p1.x), tanh_fast(p1.y),
                                tanh_fast(p1.z), tanh_fast(p1.w));
        *(float4*)&out[(size_t)row0*HH + col]     = h0;
        *(float4*)&out[(size_t)(row0+1)*HH + col] = h1;
        float* hT = &g_hT[0][0];
        const float* h0a = &h0.x;
        const float* h1a = &h1.x;
        #pragma unroll
        for (int j = 0; j < 4; j++) {
            float2 v; v.x = h0a[j]; v.y = h1a[j];
            *(float2*)&hT[(col+j)*BB + row0] = v;
        }
        hlast0 = h0; hlast1 = h1;
    }
    grid_sync();

    for (int s = 1; s < SS; s++) {
        // ---- stage h chunk: hT[(r*512+k)][bg*16..+16] -> As[k][b], k = t+j*128 ----
        {
            const float* src = &g_hT[(s-1) & 1][(size_t)(r*KH)*BB + bg*16];
            #pragma unroll
            for (int j = 0; j < 4; j++) {
                int k = t + j*128;
                const float* p = src + (size_t)k*BB;
                float4 v0 = __ldcg((const float4*)(p));
                float4 v1 = __ldcg((const float4*)(p + 4));
                float4 v2 = __ldcg((const float4*)(p + 8));
                float4 v3 = __ldcg((const float4*)(p + 12));
                float* d = &As[k*ASP];
                *(float4*)(d)      = v0;
                *(float4*)(d + 4)  = v1;
                *(float4*)(d + 8)  = v2;
                *(float4*)(d + 12) = v3;
            }
        }
        __syncthreads();

        // ---- compute: 2b x 4n per thread over k half (FMA-bound) ----
        u64 a00 = 0ull, a01 = 0ull, a10 = 0ull, a11 = 0ull;
        #pragma unroll 8
        for (int k = 0; k < KH; k++) {
            float2 av = *(const float2*)&As[k*ASP + ty*2];
            ulonglong2 w = *(const ulonglong2*)&Ws[k*64 + tx*4];
            u64 s0 = pack2s(av.x);
            u64 s1 = pack2s(av.y);
            a00 = fma2(s0, w.x, a00);
            a01 = fma2(s0, w.y, a01);
            a10 = fma2(s1, w.x, a10);
            a11 = fma2(s1, w.y, a11);
        }

        float2 c00 = unpack2(a00), c01 = unpack2(a01);
        float2 c10 = unpack2(a10), c11 = unpack2(a11);

        if (r == 0) {
            // ---- ship partial to partner via L2 + flag ----
            float4 p0 = make_float4(c00.x, c00.y, c01.x, c01.y);
            float4 p1 = make_float4(c10.x, c10.y, c11.x, c11.y);
            *(float4*)&g_pp[cl][(ty*2)*64 + tx*4]   = p0;
            *(float4*)&g_pp[cl][(ty*2+1)*64 + tx*4] = p1;
            __syncthreads();
            if (t == 0) {
                __threadfence();
                st_rlx(&g_flag[cl*32], (unsigned)s);
            }
        } else {
            // prefetch pre (independent of partner)
            float4 pre0 = *(const float4*)&g_pre[(size_t)s*BH + (size_t)row0*HH + col];
            float4 pre1 = *(const float4*)&g_pre[(size_t)s*BH + (size_t)(row0+1)*HH + col];
            // wait for partner partial (1 writer, 1 reader, ==s match)
            if (t == 0) {
                while (ld_rlx(&g_flag[cl*32]) != (unsigned)s) { }
                __threadfence();
            }
            __syncthreads();
            float4 q0 = __ldcg((const float4*)&g_pp[cl][(ty*2)*64 + tx*4]);
            float4 q1 = __ldcg((const float4*)&g_pp[cl][(ty*2+1)*64 + tx*4]);

            float4 h0 = make_float4(tanh_fast(c00.x + q0.x + pre0.x),
                                    tanh_fast(c00.y + q0.y + pre0.y),
                                    tanh_fast(c01.x + q0.z + pre0.z),
                                    tanh_fast(c01.y + q0.w + pre0.w));
            float4 h1 = make_float4(tanh_fast(c10.x + q1.x + pre1.x),
                                    tanh_fast(c10.y + q1.y + pre1.y),
                                    tanh_fast(c11.x + q1.z + pre1.z),
                                    tanh_fast(c11.y + q1.w + pre1.w));
            *(float4*)&out[(size_t)s*BH + (size_t)row0*HH + col]     = h0;
            *(float4*)&out[(size_t)s*BH + (size_t)(row0+1)*HH + col] = h1;
            float* hT = &g_hT[s & 1][0];
            const float* h0a = &h0.x;
            const float* h1a = &h1.x;
            #pragma unroll
            for (int j = 0; j < 4; j++) {
                float2 v; v.x = h0a[j]; v.y = h1a[j];
                *(float2*)&hT[(col+j)*BB + row0] = v;
            }
            hlast0 = h0; hlast1 = h1;
        }

        grid_sync();    // h_s visible grid-wide; resolves all WARs
    }

    // h_final (rank1 holds the s=511 values)
    if (r == 1) {
        *(float4*)&out[(size_t)SS*BH + (size_t)row0*HH + col]     = hlast0;
        *(float4*)&out[(size_t)SS*BH + (size_t)(row0+1)*HH + col] = hlast1;
    }
}

// =================================================================================
// Launch
// =================================================================================
extern "C" void kernel_launch(void* const* d_in, const int* in_sizes, int n_in,
                              void* d_out, int out_size) {
    const float* x  = (const float*)d_in[0];   // (S,B,I)
    const float* Ww = (const float*)d_in[1];   // (H,H)
    const float* Wb = (const float*)d_in[2];   // (H)
    const float* Vw = (const float*)d_in[3];   // (H,I)
    const float* Vb = (const float*)d_in[4];   // (H)
    float* out = (float*)d_out;                // (S,B,H) then (1,B,H)

    dim3 g1(256, 8);
    pre_gemm_kernel<<<g1, 256>>>(x, Vw, Wb, Vb);

    static int smem_set = 0;
    const int smem_bytes = (KH*64 + KH*ASP) * (int)sizeof(float);  // 172032
    if (!smem_set) {
        cudaFuncSetAttribute(rnn_recurrent_kernel,
                             cudaFuncAttributeMaxDynamicSharedMemorySize, smem_bytes);
        smem_set = 1;
    }
    rnn_recurrent_kernel<<<NB, 128, smem_bytes>>>(Ww, out);
}

// round 13
// speedup vs baseline: 1.6097x; 1.4321x over previous
#include <cuda_runtime.h>
#include <math.h>

// Problem dims
#define SS 512
#define BB 64
#define II 512
#define HH 1024
#define BH (BB*HH)

// Recurrent decomposition: 8 n-tiles (128 cols) x 16 k-chunks (64 k) = 128 blocks
#define NT 8
#define KC 16
#define NB (NT*KC)
#define ASP 68          // As row pitch in floats ([k][b] layout, 64 b + pad)

// -------------------- device scratch --------------------------------------------
__device__ float g_pre[SS*BH];        // V x_t + b_V + b_W
__device__ float g_part[KC][BH];      // split-K partials (single buffer)
__device__ float g_hT[2][HH*BB];      // parity-buffered TRANSPOSED h: hT[c][b]
__device__ unsigned g_bar_cnt = 0;
__device__ unsigned g_bar_gen = 0;

// -------------------- packed f32x2 helpers --------------------------------------
typedef unsigned long long u64;

__device__ __forceinline__ u64 pack2s(float x) {
    u64 r; asm("mov.b64 %0, {%1, %1};" : "=l"(r) : "f"(x)); return r;
}
__device__ __forceinline__ u64 fma2(u64 a, u64 b, u64 c) {
    u64 d; asm("fma.rn.f32x2 %0, %1, %2, %3;" : "=l"(d) : "l"(a), "l"(b), "l"(c));
    return d;
}
__device__ __forceinline__ float2 unpack2(u64 v) {
    float2 f; asm("mov.b64 {%0, %1}, %2;" : "=f"(f.x), "=f"(f.y) : "l"(v)); return f;
}
__device__ __forceinline__ float tanh_fast(float x) {
    float y; asm("tanh.approx.f32 %0, %1;" : "=f"(y) : "f"(x)); return y;
}

// -------------------- global ticket barrier, release/acquire version -------------
// Arrival = atom.acq_rel.gpu (releases this block's prior writes — cumulative
// through the preceding __syncthreads; acquires earlier arrivals, so the
// releaser sees everyone's writes). Release = st.release.gpu. Spin =
// ld.acquire.gpu. No fence.sc anywhere. Pre-arrival relaxed read of gen is
// exact by per-location coherence (this block observed gen at the previous
// barrier; it cannot read an older value). Replay-safe: gen is monotonic and
// compared against the sampled value.
__device__ __forceinline__ void grid_sync() {
    __syncthreads();
    if (threadIdx.x == 0) {
        unsigned gen;
        asm volatile("ld.relaxed.gpu.global.b32 %0, [%1];"
                     : "=r"(gen) : "l"(&g_bar_gen) : "memory");
        unsigned old;
        asm volatile("atom.acq_rel.gpu.global.add.u32 %0, [%1], %2;"
                     : "=r"(old) : "l"(&g_bar_cnt), "r"(1u) : "memory");
        if (old == NB - 1u) {
            asm volatile("st.relaxed.gpu.global.b32 [%0], %1;"
                         :: "l"(&g_bar_cnt), "r"(0u) : "memory");
            asm volatile("st.release.gpu.global.b32 [%0], %1;"
                         :: "l"(&g_bar_gen), "r"(gen + 1u) : "memory");
        } else {
            unsigned v;
            do {
                asm volatile("ld.acquire.gpu.global.b32 %0, [%1];"
                             : "=r"(v) : "l"(&g_bar_gen) : "memory");
            } while (v == gen);
        }
    }
    __syncthreads();
}

// =================================================================================
// Kernel 1: g_pre = x @ Vw^T + Vb + Wb  (R9/R10 conflict-free version, proven)
// =================================================================================
__global__ void __launch_bounds__(256) pre_gemm_kernel(
        const float* __restrict__ x,
        const float* __restrict__ Vw,
        const float* __restrict__ Wb,
        const float* __restrict__ Vb) {
    __shared__ float As[128][20];
    __shared__ float Ws[16][132];

    const int bm = blockIdx.x;
    const int bn = blockIdx.y;
    const int t  = threadIdx.x;
    const int tx = t & 15;
    const int ty = t >> 4;

    u64 acc[8][4];
    #pragma unroll
    for (int j = 0; j < 8; j++)
        #pragma unroll
        for (int p = 0; p < 4; p++) acc[j][p] = 0ull;

    const float* Arow = x  + (size_t)(bm*128) * II;
    const float* Wrow = Vw + (size_t)(bn*128) * II;

    for (int kb = 0; kb < II; kb += 16) {
        #pragma unroll
        for (int it = 0; it < 2; it++) {
            int q  = t + it*256;
            int r  = q >> 2;
            int k4 = (q & 3) << 2;
            float4 va = *(const float4*)(Arow + (size_t)r*II + kb + k4);
            *(float4*)&As[r][k4] = va;
            float4 vw = *(const float4*)(Wrow + (size_t)r*II + kb + k4);
            Ws[k4+0][r] = vw.x; Ws[k4+1][r] = vw.y;
            Ws[k4+2][r] = vw.z; Ws[k4+3][r] = vw.w;
        }
        __syncthreads();
        #pragma unroll
        for (int k = 0; k < 16; k++) {
            ulonglong2 w01 = *(const ulonglong2*)&Ws[k][tx*4];
            ulonglong2 w23 = *(const ulonglong2*)&Ws[k][tx*4 + 64];
            #pragma unroll
            for (int j = 0; j < 8; j++) {
                u64 ap = pack2s(As[ty*8 + j][k]);
                acc[j][0] = fma2(ap, w01.x, acc[j][0]);
                acc[j][1] = fma2(ap, w01.y, acc[j][1]);
                acc[j][2] = fma2(ap, w23.x, acc[j][2]);
                acc[j][3] = fma2(ap, w23.y, acc[j][3]);
            }
        }
        __syncthreads();
    }

    const int nb0 = bn*128 + tx*4;
    const int nb1 = nb0 + 64;
    float b0[4], b1[4];
    #pragma unroll
    for (int i = 0; i < 4; i++) {
        b0[i] = Vb[nb0+i] + Wb[nb0+i];
        b1[i] = Vb[nb1+i] + Wb[nb1+i];
    }

    #pragma unroll
    for (int j = 0; j < 8; j++) {
        size_t row = (size_t)bm*128 + ty*8 + j;
        float2 c0 = unpack2(acc[j][0]);
        float2 c1 = unpack2(acc[j][1]);
        float2 c2 = unpack2(acc[j][2]);
        float2 c3 = unpack2(acc[j][3]);
        float4 o0 = make_float4(c0.x+b0[0], c0.y+b0[1], c1.x+b0[2], c1.y+b0[3]);
        float4 o1 = make_float4(c2.x+b1[0], c2.y+b1[1], c3.x+b1[2], c3.y+b1[3]);
        *(float4*)&g_pre[row*HH + nb0] = o0;
        *(float4*)&g_pre[row*HH + nb1] = o1;
    }
}

// =================================================================================
// Kernel 2: persistent recurrence (R10 structure verbatim, cheap barriers).
//   128 threads, 8b x 8n micro (crossbar-optimal), conflict-free w loads,
//   transposed h exchange (g_hT[c][b], parity-buffered) for coalesced staging.
//   A-role (nt,kc): partial[64b][128n] over k-chunk 64; Ww slice in SMEM [k][n].
//   B-role: linear float4 slice o = (bid*128+t)*4; reduce 16 partials + tanh,
//           write out (coalesced) + hT (scattered, fire-and-forget).
// =================================================================================
__global__ void __launch_bounds__(128) rnn_recurrent_kernel(
        const float* __restrict__ Ww,
        float* __restrict__ out) {
    extern __shared__ float smem[];
    float* Ws = smem;                 // [k=64][n=128]  32 KB
    float* As = smem + 64*128;        // [k=64][b pitch ASP] 17.4 KB

    const int bid = blockIdx.x;
    const int nt  = bid & (NT-1);
    const int kc  = bid >> 3;
    const int t   = threadIdx.x;
    const int tx  = t & 15;           // n group (8 cols as tx*4 and 64+tx*4)
    const int ty  = t >> 4;           // b group (8 rows)

    // Resident Ww slice transposed: Ws[k][n] = Ww[nt*128+n][kc*64+k]
    for (int q = t; q < 128*16; q += 128) {
        int n  = q >> 4;
        int k4 = (q & 15) << 2;
        float4 v = *(const float4*)(Ww + (size_t)(nt*128 + n)*HH + kc*64 + k4);
        Ws[(k4+0)*128 + n] = v.x;
        Ws[(k4+1)*128 + n] = v.y;
        Ws[(k4+2)*128 + n] = v.z;
        Ws[(k4+3)*128 + n] = v.w;
    }

    // B-role: linear float4 slice (128 blk * 128 thr * 4 = BH)
    const int o   = (bid*128 + t)*4;
    const int ob  = o >> 10;          // batch row
    const int oc  = o & 1023;         // first of 4 consecutive cols

    // ---- step 0: h_0 = tanh(pre_0) ----
    {
        float4 p = *(const float4*)&g_pre[o];
        float4 h = make_float4(tanh_fast(p.x), tanh_fast(p.y),
                               tanh_fast(p.z), tanh_fast(p.w));
        *(float4*)&out[o] = h;
        float* hT = &g_hT[0][0];
        hT[(oc+0)*BB + ob] = h.x;
        hT[(oc+1)*BB + ob] = h.y;
        hT[(oc+2)*BB + ob] = h.z;
        hT[(oc+3)*BB + ob] = h.w;
    }
    grid_sync();

    float4 hlast = make_float4(0.f, 0.f, 0.f, 0.f);

    for (int s = 1; s < SS; s++) {
        // ---- stage hT chunk [kc*64 .. +64)[b] : fully contiguous 16KB ----
        {
            const float* src = &g_hT[(s-1) & 1][kc*64*BB];
            float* dstBase = As;
            #pragma unroll
            for (int j = 0; j < 8; j++) {
                int off4 = t + j*128;          // float4 index, 0..1023
                int kk   = off4 >> 4;          // k row (16 float4 per row)
                int b4   = (off4 & 15) << 2;   // b offset
                float4 v = __ldcg((const float4*)(src + off4*4));
                *(float4*)&dstBase[kk*ASP + b4] = v;
            }
        }
        __syncthreads();

        // ---- A compute: 8b x 8n per thread ----
        u64 acc[8][4];
        #pragma unroll
        for (int j = 0; j < 8; j++)
            #pragma unroll
            for (int p = 0; p < 4; p++) acc[j][p] = 0ull;

        #pragma unroll 4
        for (int k = 0; k < 64; k++) {
            const float* ar = As + k*ASP + ty*8;
            float4 aA = *(const float4*)(ar);      // broadcast (2 addrs/warp)
            float4 aB = *(const float4*)(ar + 4);
            const float* wr = Ws + k*128 + tx*4;
            ulonglong2 w01 = *(const ulonglong2*)(wr);        // conflict-free
            ulonglong2 w23 = *(const ulonglong2*)(wr + 64);
            u64 a;
            a = pack2s(aA.x);
            acc[0][0] = fma2(a, w01.x, acc[0][0]);
            acc[0][1] = fma2(a, w01.y, acc[0][1]);
            acc[0][2] = fma2(a, w23.x, acc[0][2]);
            acc[0][3] = fma2(a, w23.y, acc[0][3]);
            a = pack2s(aA.y);
            acc[1][0] = fma2(a, w01.x, acc[1][0]);
            acc[1][1] = fma2(a, w01.y, acc[1][1]);
            acc[1][2] = fma2(a, w23.x, acc[1][2]);
            acc[1][3] = fma2(a, w23.y, acc[1][3]);
            a = pack2s(aA.z);
            acc[2][0] = fma2(a, w01.x, acc[2][0]);
            acc[2][1] = fma2(a, w01.y, acc[2][1]);
            acc[2][2] = fma2(a, w23.x, acc[2][2]);
            acc[2][3] = fma2(a, w23.y, acc[2][3]);
            a = pack2s(aA.w);
            acc[3][0] = fma2(a, w01.x, acc[3][0]);
            acc[3][1] = fma2(a, w01.y, acc[3][1]);
            acc[3][2] = fma2(a, w23.x, acc[3][2]);
            acc[3][3] = fma2(a, w23.y, acc[3][3]);
            a = pack2s(aB.x);
            acc[4][0] = fma2(a, w01.x, acc[4][0]);
            acc[4][1] = fma2(a, w01.y, acc[4][1]);
            acc[4][2] = fma2(a, w23.x, acc[4][2]);
            acc[4][3] = fma2(a, w23.y, acc[4][3]);
            a = pack2s(aB.y);
            acc[5][0] = fma2(a, w01.x, acc[5][0]);
            acc[5][1] = fma2(a, w01.y, acc[5][1]);
            acc[5][2] = fma2(a, w23.x, acc[5][2]);
            acc[5][3] = fma2(a, w23.y, acc[5][3]);
            a = pack2s(aB.z);
            acc[6][0] = fma2(a, w01.x, acc[6][0]);
            acc[6][1] = fma2(a, w01.y, acc[6][1]);
            acc[6][2] = fma2(a, w23.x, acc[6][2]);
            acc[6][3] = fma2(a, w23.y, acc[6][3]);
            a = pack2s(aB.w);
            acc[7][0] = fma2(a, w01.x, acc[7][0]);
            acc[7][1] = fma2(a, w01.y, acc[7][1]);
            acc[7][2] = fma2(a, w23.x, acc[7][2]);
            acc[7][3] = fma2(a, w23.y, acc[7][3]);
        }

        // ---- store partials (cols tx*4 and 64+tx*4) ----
        #pragma unroll
        for (int j = 0; j < 8; j++) {
            float* dst = &g_part[kc][(size_t)(ty*8 + j)*HH + nt*128 + tx*4];
            ulonglong2 v0; v0.x = acc[j][0]; v0.y = acc[j][1];
            ulonglong2 v1; v1.x = acc[j][2]; v1.y = acc[j][3];
            *(ulonglong2*)(dst)      = v0;
            *(ulonglong2*)(dst + 64) = v1;
        }

        // prefetch pre for B-role (independent of partials)
        float4 pre4 = *(const float4*)&g_pre[(size_t)s*BH + o];

        grid_sync();    // all partials(s) visible

        // ---- B reduce + tanh + write h_s (out coalesced, hT scattered) ----
        {
            float4 a4 = pre4;
            #pragma unroll
            for (int kk = 0; kk < KC; kk++) {
                float4 p = __ldcg((const float4*)&g_part[kk][o]);
                a4.x += p.x; a4.y += p.y; a4.z += p.z; a4.w += p.w;
            }
            float4 h = make_float4(tanh_fast(a4.x), tanh_fast(a4.y),
                                   tanh_fast(a4.z), tanh_fast(a4.w));
            float* hT = &g_hT[s & 1][0];
            hT[(oc+0)*BB + ob] = h.x;
            hT[(oc+1)*BB + ob] = h.y;
            hT[(oc+2)*BB + ob] = h.z;
            hT[(oc+3)*BB + ob] = h.w;
            *(float4*)&out[(size_t)s*BH + o] = h;
            hlast = h;
        }

        grid_sync();    // h_s (hT) visible; also guards partial-buffer WAR
    }

    // h_final: values this thread computed at s=511
    *(float4*)&out[(size_t)SS*BH + o] = hlast;
}

// =================================================================================
// Launch
// =================================================================================
extern "C" void kernel_launch(void* const* d_in, const int* in_sizes, int n_in,
                              void* d_out, int out_size) {
    const float* x  = (const float*)d_in[0];   // (S,B,I)
    const float* Ww = (const float*)d_in[1];   // (H,H)
    const float* Wb = (const float*)d_in[2];   // (H)
    const float* Vw = (const float*)d_in[3];   // (H,I)
    const float* Vb = (const float*)d_in[4];   // (H)
    float* out = (float*)d_out;                // (S,B,H) then (1,B,H)

    dim3 g1(256, 8);
    pre_gemm_kernel<<<g1, 256>>>(x, Vw, Wb, Vb);

    static int smem_set = 0;
    const int smem_bytes = (64*128 + 64*ASP) * (int)sizeof(float);  // 50176
    if (!smem_set) {
        cudaFuncSetAttribute(rnn_recurrent_kernel,
                             cudaFuncAttributeMaxDynamicSharedMemorySize, smem_bytes);
        smem_set = 1;
    }
    rnn_recurrent_kernel<<<NB, 128, smem_bytes>>>(Ww, out);
}

// round 15
// speedup vs baseline: 1.7250x; 1.0716x over previous
#include <cuda_runtime.h>
#include <cuda_bf16.h>
#include <math.h>
#include <cstdint>

// Problem dims
#define SS 512
#define BB 64
#define II 512
#define HH 1024
#define BH (BB*HH)

// Recurrent decomposition (R13, proven): 8 nt x 16 kc = 128 blocks
#define NT 8
#define KC 16
#define NB (NT*KC)
#define ASP 68

// -------------------- device scratch --------------------------------------------
__device__ float g_pre[SS*BH];
__device__ float g_part[KC][BH];
__device__ float g_hT[2][HH*BB];
__device__ unsigned g_bar_cnt = 0;
__device__ unsigned g_bar_gen = 0;
// split-bf16 operands for the pre-GEMM
__device__ __nv_bfloat16 g_xhi[SS*BB*II];
__device__ __nv_bfloat16 g_xlo[SS*BB*II];
__device__ __nv_bfloat16 g_vhi[HH*II];
__device__ __nv_bfloat16 g_vlo[HH*II];

// -------------------- packed f32x2 helpers --------------------------------------
typedef unsigned long long u64;

__device__ __forceinline__ u64 pack2s(float x) {
    u64 r; asm("mov.b64 %0, {%1, %1};" : "=l"(r) : "f"(x)); return r;
}
__device__ __forceinline__ u64 fma2(u64 a, u64 b, u64 c) {
    u64 d; asm("fma.rn.f32x2 %0, %1, %2, %3;" : "=l"(d) : "l"(a), "l"(b), "l"(c));
    return d;
}
__device__ __forceinline__ float tanh_fast(float x) {
    float y; asm("tanh.approx.f32 %0, %1;" : "=f"(y) : "f"(x)); return y;
}

// -------------------- global ticket barrier (R13 release/acquire) ----------------
__device__ __forceinline__ void grid_sync() {
    __syncthreads();
    if (threadIdx.x == 0) {
        unsigned gen;
        asm volatile("ld.relaxed.gpu.global.b32 %0, [%1];"
                     : "=r"(gen) : "l"(&g_bar_gen) : "memory");
        unsigned old;
        asm volatile("atom.acq_rel.gpu.global.add.u32 %0, [%1], %2;"
                     : "=r"(old) : "l"(&g_bar_cnt), "r"(1u) : "memory");
        if (old == NB - 1u) {
            asm volatile("st.relaxed.gpu.global.b32 [%0], %1;"
                         :: "l"(&g_bar_cnt), "r"(0u) : "memory");
            asm volatile("st.release.gpu.global.b32 [%0], %1;"
                         :: "l"(&g_bar_gen), "r"(gen + 1u) : "memory");
        } else {
            unsigned v;
            do {
                asm volatile("ld.acquire.gpu.global.b32 %0, [%1];"
                             : "=r"(v) : "l"(&g_bar_gen) : "memory");
            } while (v == gen);
        }
    }
    __syncthreads();
}

// =================================================================================
// Split-bf16 conversion: hi = bf16(v), lo = bf16(v - hi)
// =================================================================================
__global__ void convert_split_kernel(const float* __restrict__ src,
                                     __nv_bfloat16* __restrict__ hi,
                                     __nv_bfloat16* __restrict__ lo, int n) {
    for (int i = blockIdx.x*blockDim.x + threadIdx.x; i < n;
         i += gridDim.x*blockDim.x) {
        float v = src[i];
        __nv_bfloat16 h = __float2bfloat16(v);
        float r = v - __bfloat162float(h);
        hi[i] = h;
        lo[i] = __float2bfloat16(r);
    }
}

// =================================================================================
// HMMA pre-GEMM: g_pre = x @ Vw^T + Vb + Wb  (3-term split-bf16, mma.sync)
//   Block tile 128m x 128n, BK=16, 256 thr = 8 warps (4m x 2n), warp = 32m x 64n.
//   Smem rows padded to 24 bf16 (48 B) -> 16B-aligned, ldmatrix conflict-free.
// =================================================================================
#define SROW 24    // bf16 elements per smem row (16 data + 8 pad)

__device__ __forceinline__ void ldsm_x4(uint32_t& r0, uint32_t& r1,
                                        uint32_t& r2, uint32_t& r3, uint32_t a) {
    asm volatile("ldmatrix.sync.aligned.m8n8.x4.shared.b16 {%0,%1,%2,%3}, [%4];"
                 : "=r"(r0), "=r"(r1), "=r"(r2), "=r"(r3) : "r"(a));
}
__device__ __forceinline__ void ldsm_x2(uint32_t& r0, uint32_t& r1, uint32_t a) {
    asm volatile("ldmatrix.sync.aligned.m8n8.x2.shared.b16 {%0,%1}, [%2];"
                 : "=r"(r0), "=r"(r1) : "r"(a));
}
__device__ __forceinline__ void mma_bf16(float* c, const uint32_t* a,
                                         uint32_t b0, uint32_t b1) {
    asm volatile(
        "mma.sync.aligned.m16n8k16.row.col.f32.bf16.bf16.f32 "
        "{%0,%1,%2,%3}, {%4,%5,%6,%7}, {%8,%9}, {%0,%1,%2,%3};"
        : "+f"(c[0]), "+f"(c[1]), "+f"(c[2]), "+f"(c[3])
        : "r"(a[0]), "r"(a[1]), "r"(a[2]), "r"(a[3]), "r"(b0), "r"(b1));
}
__device__ __forceinline__ uint32_t smem_u32(const void* p) {
    uint32_t a;
    asm("{ .reg .u64 t; cvta.to.shared.u64 t, %1; cvt.u32.u64 %0, t; }"
        : "=r"(a) : "l"(p));
    return a;
}

__global__ void __launch_bounds__(256, 2) pre_hmma_kernel(
        const float* __restrict__ Wb, const float* __restrict__ Vb) {
    __shared__ __nv_bfloat16 sAh[128*SROW];
    __shared__ __nv_bfloat16 sAl[128*SROW];
    __shared__ __nv_bfloat16 sBh[128*SROW];
    __shared__ __nv_bfloat16 sBl[128*SROW];

    const int bm = blockIdx.x;         // 0..255
    const int bn = blockIdx.y;         // 0..7
    const int t  = threadIdx.x;
    const int w  = t >> 5;
    const int lane = t & 31;
    const int wm = w & 3;              // m group of 32
    const int wn = w >> 2;             // n group of 64

    // global load mapping (one uint4 = 8 bf16 per tile per thread per iter)
    const int grow = t >> 1;           // 0..127
    const int gc8  = (t & 1) * 8;      // 0 or 8

    const __nv_bfloat16* Ah = g_xhi + (size_t)(bm*128 + grow)*II + gc8;
    const __nv_bfloat16* Al = g_xlo + (size_t)(bm*128 + grow)*II + gc8;
    const __nv_bfloat16* Bh = g_vhi + (size_t)(bn*128 + grow)*II + gc8;
    const __nv_bfloat16* Bl = g_vlo + (size_t)(bn*128 + grow)*II + gc8;

    __nv_bfloat16* dA_h = &sAh[grow*SROW + gc8];
    __nv_bfloat16* dA_l = &sAl[grow*SROW + gc8];
    __nv_bfloat16* dB_h = &sBh[grow*SROW + gc8];
    __nv_bfloat16* dB_l = &sBl[grow*SROW + gc8];

    // ldmatrix addresses
    const uint32_t baseAh = smem_u32(sAh);
    const uint32_t baseAl = smem_u32(sAl);
    const uint32_t baseBh = smem_u32(sBh);
    const uint32_t baseBl = smem_u32(sBl);
    const uint32_t aoff = (uint32_t)(((wm*32 + (lane & 15))*SROW + ((lane >> 4) & 1)*8) * 2);
    const uint32_t boff = (uint32_t)(((wn*64 + (lane & 7))*SROW + ((lane >> 3) & 1)*8) * 2);

    float acc[2][8][4];
    #pragma unroll
    for (int mf = 0; mf < 2; mf++)
        #pragma unroll
        for (int nf = 0; nf < 8; nf++)
            #pragma unroll
            for (int q = 0; q < 4; q++) acc[mf][nf][q] = 0.f;

    for (int kb = 0; kb < II/16; kb++) {
        uint4 va_h = *(const uint4*)(Ah + kb*16);
        uint4 va_l = *(const uint4*)(Al + kb*16);
        uint4 vb_h = *(const uint4*)(Bh + kb*16);
        uint4 vb_l = *(const uint4*)(Bl + kb*16);
        __syncthreads();
        *(uint4*)dA_h = va_h;
        *(uint4*)dA_l = va_l;
        *(uint4*)dB_h = vb_h;
        *(uint4*)dB_l = vb_l;
        __syncthreads();

        uint32_t ah[2][4], al[2][4];
        #pragma unroll
        for (int mf = 0; mf < 2; mf++) {
            uint32_t off = aoff + (uint32_t)(mf*16*SROW*2);
            ldsm_x4(ah[mf][0], ah[mf][1], ah[mf][2], ah[mf][3], baseAh + off);
            ldsm_x4(al[mf][0], al[mf][1], al[mf][2], al[mf][3], baseAl + off);
        }
        #pragma unroll
        for (int nf = 0; nf < 8; nf++) {
            uint32_t off = boff + (uint32_t)(nf*8*SROW*2);
            uint32_t bh0, bh1, bl0, bl1;
            ldsm_x2(bh0, bh1, baseBh + off);
            ldsm_x2(bl0, bl1, baseBl + off);
            #pragma unroll
            for (int mf = 0; mf < 2; mf++) {
                mma_bf16(acc[mf][nf], ah[mf], bh0, bh1);   // hi*hi
                mma_bf16(acc[mf][nf], ah[mf], bl0, bl1);   // hi*lo
                mma_bf16(acc[mf][nf], al[mf], bh0, bh1);   // lo*hi
            }
        }
    }

    // epilogue: + (Vb+Wb), store fp32
    #pragma unroll
    for (int nf = 0; nf < 8; nf++) {
        int col = bn*128 + wn*64 + nf*8 + (lane & 3)*2;
        float b0 = Vb[col]   + Wb[col];
        float b1 = Vb[col+1] + Wb[col+1];
        #pragma unroll
        for (int mf = 0; mf < 2; mf++) {
            size_t row = (size_t)(bm*128 + wm*32 + mf*16 + (lane >> 2));
            float2 o0 = make_float2(acc[mf][nf][0] + b0, acc[mf][nf][1] + b1);
            float2 o1 = make_float2(acc[mf][nf][2] + b0, acc[mf][nf][3] + b1);
            *(float2*)&g_pre[row*HH + col]       = o0;
            *(float2*)&g_pre[(row+8)*HH + col]   = o1;
        }
    }
}

// =================================================================================
// Kernel 2: persistent recurrence — R13 VERBATIM (proven best, 5276us)
// =================================================================================
__global__ void __launch_bounds__(128) rnn_recurrent_kernel(
        const float* __restrict__ Ww,
        float* __restrict__ out) {
    extern __shared__ float smemf[];
    float* Ws = smemf;                // [k=64][n=128]  32 KB
    float* As = smemf + 64*128;       // [k=64][b pitch ASP]

    const int bid = blockIdx.x;
    const int nt  = bid & (NT-1);
    const int kc  = bid >> 3;
    const int t   = threadIdx.x;
    const int tx  = t & 15;
    const int ty  = t >> 4;

    for (int q = t; q < 128*16; q += 128) {
        int n  = q >> 4;
        int k4 = (q & 15) << 2;
        float4 v = *(const float4*)(Ww + (size_t)(nt*128 + n)*HH + kc*64 + k4);
        Ws[(k4+0)*128 + n] = v.x;
        Ws[(k4+1)*128 + n] = v.y;
        Ws[(k4+2)*128 + n] = v.z;
        Ws[(k4+3)*128 + n] = v.w;
    }

    const int o   = (bid*128 + t)*4;
    const int ob  = o >> 10;
    const int oc  = o & 1023;

    {
        float4 p = *(const float4*)&g_pre[o];
        float4 h = make_float4(tanh_fast(p.x), tanh_fast(p.y),
                               tanh_fast(p.z), tanh_fast(p.w));
        *(float4*)&out[o] = h;
        float* hT = &g_hT[0][0];
        hT[(oc+0)*BB + ob] = h.x;
        hT[(oc+1)*BB + ob] = h.y;
        hT[(oc+2)*BB + ob] = h.z;
        hT[(oc+3)*BB + ob] = h.w;
    }
    grid_sync();

    float4 hlast = make_float4(0.f, 0.f, 0.f, 0.f);

    for (int s = 1; s < SS; s++) {
        {
            const float* src = &g_hT[(s-1) & 1][kc*64*BB];
            #pragma unroll
            for (int j = 0; j < 8; j++) {
                int off4 = t + j*128;
                int kk   = off4 >> 4;
                int b4   = (off4 & 15) << 2;
                float4 v = __ldcg((const float4*)(src + off4*4));
                *(float4*)&As[kk*ASP + b4] = v;
            }
        }
        __syncthreads();

        u64 acc[8][4];
        #pragma unroll
        for (int j = 0; j < 8; j++)
            #pragma unroll
            for (int p = 0; p < 4; p++) acc[j][p] = 0ull;

        #pragma unroll 4
        for (int k = 0; k < 64; k++) {
            const float* ar = As + k*ASP + ty*8;
            float4 aA = *(const float4*)(ar);
            float4 aB = *(const float4*)(ar + 4);
            const float* wr = Ws + k*128 + tx*4;
            ulonglong2 w01 = *(const ulonglong2*)(wr);
            ulonglong2 w23 = *(const ulonglong2*)(wr + 64);
            u64 a;
            a = pack2s(aA.x);
            acc[0][0] = fma2(a, w01.x, acc[0][0]);
            acc[0][1] = fma2(a, w01.y, acc[0][1]);
            acc[0][2] = fma2(a, w23.x, acc[0][2]);
            acc[0][3] = fma2(a, w23.y, acc[0][3]);
            a = pack2s(aA.y);
            acc[1][0] = fma2(a, w01.x, acc[1][0]);
            acc[1][1] = fma2(a, w01.y, acc[1][1]);
            acc[1][2] = fma2(a, w23.x, acc[1][2]);
            acc[1][3] = fma2(a, w23.y, acc[1][3]);
            a = pack2s(aA.z);
            acc[2][0] = fma2(a, w01.x, acc[2][0]);
            acc[2][1] = fma2(a, w01.y, acc[2][1]);
            acc[2][2] = fma2(a, w23.x, acc[2][2]);
            acc[2][3] = fma2(a, w23.y, acc[2][3]);
            a = pack2s(aA.w);
            acc[3][0] = fma2(a, w01.x, acc[3][0]);
            acc[3][1] = fma2(a, w01.y, acc[3][1]);
            acc[3][2] = fma2(a, w23.x, acc[3][2]);
            acc[3][3] = fma2(a, w23.y, acc[3][3]);
            a = pack2s(aB.x);
            acc[4][0] = fma2(a, w01.x, acc[4][0]);
            acc[4][1] = fma2(a, w01.y, acc[4][1]);
            acc[4][2] = fma2(a, w23.x, acc[4][2]);
            acc[4][3] = fma2(a, w23.y, acc[4][3]);
            a = pack2s(aB.y);
            acc[5][0] = fma2(a, w01.x, acc[5][0]);
            acc[5][1] = fma2(a, w01.y, acc[5][1]);
            acc[5][2] = fma2(a, w23.x, acc[5][2]);
            acc[5][3] = fma2(a, w23.y, acc[5][3]);
            a = pack2s(aB.z);
            acc[6][0] = fma2(a, w01.x, acc[6][0]);
            acc[6][1] = fma2(a, w01.y, acc[6][1]);
            acc[6][2] = fma2(a, w23.x, acc[6][2]);
            acc[6][3] = fma2(a, w23.y, acc[6][3]);
            a = pack2s(aB.w);
            acc[7][0] = fma2(a, w01.x, acc[7][0]);
            acc[7][1] = fma2(a, w01.y, acc[7][1]);
            acc[7][2] = fma2(a, w23.x, acc[7][2]);
            acc[7][3] = fma2(a, w23.y, acc[7][3]);
        }

        #pragma unroll
        for (int j = 0; j < 8; j++) {
            float* dst = &g_part[kc][(size_t)(ty*8 + j)*HH + nt*128 + tx*4];
            ulonglong2 v0; v0.x = acc[j][0]; v0.y = acc[j][1];
            ulonglong2 v1; v1.x = acc[j][2]; v1.y = acc[j][3];
            *(ulonglong2*)(dst)      = v0;
            *(ulonglong2*)(dst + 64) = v1;
        }

        float4 pre4 = *(const float4*)&g_pre[(size_t)s*BH + o];

        grid_sync();

        {
            float4 a4 = pre4;
            #pragma unroll
            for (int kk = 0; kk < KC; kk++) {
                float4 p = __ldcg((const float4*)&g_part[kk][o]);
                a4.x += p.x; a4.y += p.y; a4.z += p.z; a4.w += p.w;
            }
            float4 h = make_float4(tanh_fast(a4.x), tanh_fast(a4.y),
                                   tanh_fast(a4.z), tanh_fast(a4.w));
            float* hT = &g_hT[s & 1][0];
            hT[(oc+0)*BB + ob] = h.x;
            hT[(oc+1)*BB + ob] = h.y;
            hT[(oc+2)*BB + ob] = h.z;
            hT[(oc+3)*BB + ob] = h.w;
            *(float4*)&out[(size_t)s*BH + o] = h;
            hlast = h;
        }

        grid_sync();
    }

    *(float4*)&out[(size_t)SS*BH + o] = hlast;
}

// =================================================================================
// Launch
// =================================================================================
extern "C" void kernel_launch(void* const* d_in, const int* in_sizes, int n_in,
                              void* d_out, int out_size) {
    const float* x  = (const float*)d_in[0];   // (S,B,I)
    const float* Ww = (const float*)d_in[1];   // (H,H)
    const float* Wb = (const float*)d_in[2];   // (H)
    const float* Vw = (const float*)d_in[3];   // (H,I)
    const float* Vb = (const float*)d_in[4];   // (H)
    float* out = (float*)d_out;                // (S,B,H) then (1,B,H)

    static int attr_set = 0;
    const int rnn_smem = (64*128 + 64*ASP) * (int)sizeof(float);   // 50176
    if (!attr_set) {
        cudaFuncSetAttribute(rnn_recurrent_kernel,
                             cudaFuncAttributeMaxDynamicSharedMemorySize, rnn_smem);
        attr_set = 1;
    }

    // split-bf16 conversions
    __nv_bfloat16 *xhi, *xlo, *vhi, *vlo;
    cudaGetSymbolAddress((void**)&xhi, g_xhi);
    cudaGetSymbolAddress((void**)&xlo, g_xlo);
    cudaGetSymbolAddress((void**)&vhi, g_vhi);
    cudaGetSymbolAddress((void**)&vlo, g_vlo);
    convert_split_kernel<<<4096, 256>>>(x, xhi, xlo, SS*BB*II);
    convert_split_kernel<<<512, 256>>>(Vw, vhi, vlo, HH*II);

    // HMMA pre-GEMM
    dim3 gmma(256, 8);
    pre_hmma_kernel<<<gmma, 256>>>(Wb, Vb);

    // persistent recurrence (R13 verbatim)
    rnn_recurrent_kernel<<<NB, 128, rnn_smem>>>(Ww, out);
}

// round 16
// speedup vs baseline: 1.8565x; 1.0763x over previous
#include <cuda_runtime.h>
#include <cuda_bf16.h>
#include <math.h>
#include <cstdint>

// Problem dims
#define SS 512
#define BB 64
#define II 512
#define HH 1024
#define BH (BB*HH)

// Recurrent decomposition (R13 structure): 8 nt x 16 kc = 128 blocks
#define NT 8
#define KC 16
#define NB (NT*KC)
#define AP 72          // bf16 row pitch for staged A / W smem (64 + 8 pad)

// -------------------- device scratch --------------------------------------------
__device__ float g_pre[SS*BH];
__device__ float g_part[KC][BH];
__device__ __nv_bfloat16 g_hTh[2][HH*BB];   // parity transposed h, hi part [c][b]
__device__ __nv_bfloat16 g_hTl[2][HH*BB];   // lo part
__device__ unsigned g_bar_cnt = 0;
__device__ unsigned g_bar_gen = 0;
// split-bf16 operands for the pre-GEMM
__device__ __nv_bfloat16 g_xhi[SS*BB*II];
__device__ __nv_bfloat16 g_xlo[SS*BB*II];
__device__ __nv_bfloat16 g_vhi[HH*II];
__device__ __nv_bfloat16 g_vlo[HH*II];

__device__ __forceinline__ float tanh_fast(float x) {
    float y; asm("tanh.approx.f32 %0, %1;" : "=f"(y) : "f"(x)); return y;
}

// -------------------- global ticket barrier (R13 release/acquire) ----------------
__device__ __forceinline__ void grid_sync() {
    __syncthreads();
    if (threadIdx.x == 0) {
        unsigned gen;
        asm volatile("ld.relaxed.gpu.global.b32 %0, [%1];"
                     : "=r"(gen) : "l"(&g_bar_gen) : "memory");
        unsigned old;
        asm volatile("atom.acq_rel.gpu.global.add.u32 %0, [%1], %2;"
                     : "=r"(old) : "l"(&g_bar_cnt), "r"(1u) : "memory");
        if (old == NB - 1u) {
            asm volatile("st.relaxed.gpu.global.b32 [%0], %1;"
                         :: "l"(&g_bar_cnt), "r"(0u) : "memory");
            asm volatile("st.release.gpu.global.b32 [%0], %1;"
                         :: "l"(&g_bar_gen), "r"(gen + 1u) : "memory");
        } else {
            unsigned v;
            do {
                asm volatile("ld.acquire.gpu.global.b32 %0, [%1];"
                             : "=r"(v) : "l"(&g_bar_gen) : "memory");
            } while (v == gen);
        }
    }
    __syncthreads();
}

// -------------------- MMA helpers ------------------------------------------------
__device__ __forceinline__ void ldsm_x4(uint32_t& r0, uint32_t& r1,
                                        uint32_t& r2, uint32_t& r3, uint32_t a) {
    asm volatile("ldmatrix.sync.aligned.m8n8.x4.shared.b16 {%0,%1,%2,%3}, [%4];"
                 : "=r"(r0), "=r"(r1), "=r"(r2), "=r"(r3) : "r"(a));
}
__device__ __forceinline__ void ldsm_x4t(uint32_t& r0, uint32_t& r1,
                                         uint32_t& r2, uint32_t& r3, uint32_t a) {
    asm volatile("ldmatrix.sync.aligned.m8n8.x4.trans.shared.b16 {%0,%1,%2,%3}, [%4];"
                 : "=r"(r0), "=r"(r1), "=r"(r2), "=r"(r3) : "r"(a));
}
__device__ __forceinline__ void ldsm_x2(uint32_t& r0, uint32_t& r1, uint32_t a) {
    asm volatile("ldmatrix.sync.aligned.m8n8.x2.shared.b16 {%0,%1}, [%2];"
                 : "=r"(r0), "=r"(r1) : "r"(a));
}
__device__ __forceinline__ void mma_bf16(float* c, const uint32_t* a,
                                         uint32_t b0, uint32_t b1) {
    asm volatile(
        "mma.sync.aligned.m16n8k16.row.col.f32.bf16.bf16.f32 "
        "{%0,%1,%2,%3}, {%4,%5,%6,%7}, {%8,%9}, {%0,%1,%2,%3};"
        : "+f"(c[0]), "+f"(c[1]), "+f"(c[2]), "+f"(c[3])
        : "r"(a[0]), "r"(a[1]), "r"(a[2]), "r"(a[3]), "r"(b0), "r"(b1));
}
__device__ __forceinline__ uint32_t smem_u32(const void* p) {
    uint32_t a;
    asm("{ .reg .u64 t; cvta.to.shared.u64 t, %1; cvt.u32.u64 %0, t; }"
        : "=r"(a) : "l"(p));
    return a;
}

// =================================================================================
// Split-bf16 conversion: hi = bf16(v), lo = bf16(v - hi)
// =================================================================================
__global__ void convert_split_kernel(const float* __restrict__ src,
                                     __nv_bfloat16* __restrict__ hi,
                                     __nv_bfloat16* __restrict__ lo, int n) {
    for (int i = blockIdx.x*blockDim.x + threadIdx.x; i < n;
         i += gridDim.x*blockDim.x) {
        float v = src[i];
        __nv_bfloat16 h = __float2bfloat16(v);
        float r = v - __bfloat162float(h);
        hi[i] = h;
        lo[i] = __float2bfloat16(r);
    }
}

// =================================================================================
// HMMA pre-GEMM (R15 verbatim, proven): g_pre = x @ Vw^T + Vb + Wb
// =================================================================================
#define SROW 24

__global__ void __launch_bounds__(256, 2) pre_hmma_kernel(
        const float* __restrict__ Wb, const float* __restrict__ Vb) {
    __shared__ __nv_bfloat16 sAh[128*SROW];
    __shared__ __nv_bfloat16 sAl[128*SROW];
    __shared__ __nv_bfloat16 sBh[128*SROW];
    __shared__ __nv_bfloat16 sBl[128*SROW];

    const int bm = blockIdx.x;
    const int bn = blockIdx.y;
    const int t  = threadIdx.x;
    const int w  = t >> 5;
    const int lane = t & 31;
    const int wm = w & 3;
    const int wn = w >> 2;

    const int grow = t >> 1;
    const int gc8  = (t & 1) * 8;

    const __nv_bfloat16* Ah = g_xhi + (size_t)(bm*128 + grow)*II + gc8;
    const __nv_bfloat16* Al = g_xlo + (size_t)(bm*128 + grow)*II + gc8;
    const __nv_bfloat16* Bh = g_vhi + (size_t)(bn*128 + grow)*II + gc8;
    const __nv_bfloat16* Bl = g_vlo + (size_t)(bn*128 + grow)*II + gc8;

    __nv_bfloat16* dA_h = &sAh[grow*SROW + gc8];
    __nv_bfloat16* dA_l = &sAl[grow*SROW + gc8];
    __nv_bfloat16* dB_h = &sBh[grow*SROW + gc8];
    __nv_bfloat16* dB_l = &sBl[grow*SROW + gc8];

    const uint32_t baseAh = smem_u32(sAh);
    const uint32_t baseAl = smem_u32(sAl);
    const uint32_t baseBh = smem_u32(sBh);
    const uint32_t baseBl = smem_u32(sBl);
    const uint32_t aoff = (uint32_t)(((wm*32 + (lane & 15))*SROW + ((lane >> 4) & 1)*8) * 2);
    const uint32_t boff = (uint32_t)(((wn*64 + (lane & 7))*SROW + ((lane >> 3) & 1)*8) * 2);

    float acc[2][8][4];
    #pragma unroll
    for (int mf = 0; mf < 2; mf++)
        #pragma unroll
        for (int nf = 0; nf < 8; nf++)
            #pragma unroll
            for (int q = 0; q < 4; q++) acc[mf][nf][q] = 0.f;

    for (int kb = 0; kb < II/16; kb++) {
        uint4 va_h = *(const uint4*)(Ah + kb*16);
        uint4 va_l = *(const uint4*)(Al + kb*16);
        uint4 vb_h = *(const uint4*)(Bh + kb*16);
        uint4 vb_l = *(const uint4*)(Bl + kb*16);
        __syncthreads();
        *(uint4*)dA_h = va_h;
        *(uint4*)dA_l = va_l;
        *(uint4*)dB_h = vb_h;
        *(uint4*)dB_l = vb_l;
        __syncthreads();

        uint32_t ah[2][4], al[2][4];
        #pragma unroll
        for (int mf = 0; mf < 2; mf++) {
            uint32_t off = aoff + (uint32_t)(mf*16*SROW*2);
            ldsm_x4(ah[mf][0], ah[mf][1], ah[mf][2], ah[mf][3], baseAh + off);
            ldsm_x4(al[mf][0], al[mf][1], al[mf][2], al[mf][3], baseAl + off);
        }
        #pragma unroll
        for (int nf = 0; nf < 8; nf++) {
            uint32_t off = boff + (uint32_t)(nf*8*SROW*2);
            uint32_t bh0, bh1, bl0, bl1;
            ldsm_x2(bh0, bh1, baseBh + off);
            ldsm_x2(bl0, bl1, baseBl + off);
            #pragma unroll
            for (int mf = 0; mf < 2; mf++) {
                mma_bf16(acc[mf][nf], ah[mf], bh0, bh1);
                mma_bf16(acc[mf][nf], ah[mf], bl0, bl1);
                mma_bf16(acc[mf][nf], al[mf], bh0, bh1);
            }
        }
    }

    #pragma unroll
    for (int nf = 0; nf < 8; nf++) {
        int col = bn*128 + wn*64 + nf*8 + (lane & 3)*2;
        float b0 = Vb[col]   + Wb[col];
        float b1 = Vb[col+1] + Wb[col+1];
        #pragma unroll
        for (int mf = 0; mf < 2; mf++) {
            size_t row = (size_t)(bm*128 + wm*32 + mf*16 + (lane >> 2));
            float2 o0 = make_float2(acc[mf][nf][0] + b0, acc[mf][nf][1] + b1);
            float2 o1 = make_float2(acc[mf][nf][2] + b0, acc[mf][nf][3] + b1);
            *(float2*)&g_pre[row*HH + col]       = o0;
            *(float2*)&g_pre[(row+8)*HH + col]   = o1;
        }
    }
}

// =================================================================================
// Kernel 2: persistent recurrence — R13 structure, HMMA phase A.
//   Block (nt,kc): partial[64b][128n] over k-chunk 64 via mma.sync, 3-term
//   split-bf16. Ww fragments resident in REGISTERS (converted once at startup).
//   h exchanged as split-bf16 (g_hTh/g_hTl, [c][b], parity). B-phase: fp32
//   reduce of 16 partials + pre, tanh, write out fp32 + hT hi/lo.
// =================================================================================
__global__ void __launch_bounds__(128) rnn_recurrent_kernel(
        const float* __restrict__ Ww,
        float* __restrict__ out) {
    extern __shared__ __nv_bfloat16 smb[];
    __nv_bfloat16* Ah = smb;               // [k=64][AP]  9216 B
    __nv_bfloat16* Al = smb + 64*AP;       // [k=64][AP]  9216 B
    // W conversion staging (startup only; overlaps nothing live):
    __nv_bfloat16* Whs = smb;              // [n=128][AP] 18432 B
    __nv_bfloat16* Wls = smb + 128*AP;     // [n=128][AP] 18432 B

    const int bid = blockIdx.x;
    const int nt  = bid & (NT-1);
    const int kc  = bid >> 3;
    const int t   = threadIdx.x;
    const int w   = t >> 5;               // warp 0..3: n cols [w*32, +32)
    const int lane = t & 31;

    // ---- startup: convert Ww slice to split-bf16, load fragments to regs ----
    for (int q = t; q < 128*64; q += 128) {
        int n = q >> 6, k = q & 63;
        float v = Ww[(size_t)(nt*128 + n)*HH + kc*64 + k];
        __nv_bfloat16 h = __float2bfloat16(v);
        Whs[n*AP + k] = h;
        Wls[n*AP + k] = __float2bfloat16(v - __bfloat162float(h));
    }
    __syncthreads();

    uint32_t wh[4][4][2], wl[4][4][2];     // [ntile][kstep][2 regs]
    {
        const uint32_t bWh = smem_u32(Whs);
        const uint32_t bWl = smem_u32(Wls);
        const int i  = lane & 7;
        const int sel = (lane >> 3) & 1;
        #pragma unroll
        for (int n4 = 0; n4 < 4; n4++)
            #pragma unroll
            for (int ks = 0; ks < 4; ks++) {
                uint32_t off = (uint32_t)(((w*32 + n4*8 + i)*AP + ks*16 + sel*8) * 2);
                ldsm_x2(wh[n4][ks][0], wh[n4][ks][1], bWh + off);
                ldsm_x2(wl[n4][ks][0], wl[n4][ks][1], bWl + off);
            }
    }
    __syncthreads();   // W smem no longer needed; reuse as Ah/Al

    const uint32_t bAh = smem_u32(Ah);
    const uint32_t bAl = smem_u32(Al);
    // trans-ldsm lane offset: rows k, col m
    const int li  = lane & 7;
    const int mq  = ((lane >> 3) & 1) * 8;
    const int kq  = ((lane >> 4) & 1) * 8;

    // B-role: linear float4 slice
    const int o   = (bid*128 + t)*4;
    const int ob  = o >> 10;
    const int oc  = o & 1023;

    // ---- step 0: h_0 = tanh(pre_0) ----
    {
        float4 p = *(const float4*)&g_pre[o];
        float hv[4] = { tanh_fast(p.x), tanh_fast(p.y), tanh_fast(p.z), tanh_fast(p.w) };
        *(float4*)&out[o] = make_float4(hv[0], hv[1], hv[2], hv[3]);
        #pragma unroll
        for (int j = 0; j < 4; j++) {
            __nv_bfloat16 hh = __float2bfloat16(hv[j]);
            g_hTh[0][(oc+j)*BB + ob] = hh;
            g_hTl[0][(oc+j)*BB + ob] = __float2bfloat16(hv[j] - __bfloat162float(hh));
        }
    }
    grid_sync();

    float4 hlast = make_float4(0.f, 0.f, 0.f, 0.f);

    for (int s = 1; s < SS; s++) {
        // ---- stage h chunk (split-bf16) into Ah/Al [k][b], contiguous copy ----
        {
            const __nv_bfloat16* sh = &g_hTh[(s-1) & 1][kc*64*BB];
            const __nv_bfloat16* sl = &g_hTl[(s-1) & 1][kc*64*BB];
            #pragma unroll
            for (int j = 0; j < 4; j++) {
                int off8 = t + j*128;          // 8-bf16 unit index, 0..511
                int k    = off8 >> 3;
                int b8   = (off8 & 7) * 8;
                uint4 vh = __ldcg((const uint4*)(sh + off8*8));
                uint4 vl = __ldcg((const uint4*)(sl + off8*8));
                *(uint4*)&Ah[k*AP + b8] = vh;
                *(uint4*)&Al[k*AP + b8] = vl;
            }
        }
        __syncthreads();

        // ---- A compute: HMMA, m=64 (4 tiles), warp-n 32 (4 tiles), k=64 ----
        float acc[4][4][4];
        #pragma unroll
        for (int mt = 0; mt < 4; mt++)
            #pragma unroll
            for (int n4 = 0; n4 < 4; n4++)
                #pragma unroll
                for (int q = 0; q < 4; q++) acc[mt][n4][q] = 0.f;

        #pragma unroll
        for (int ks = 0; ks < 4; ks++) {
            #pragma unroll
            for (int mt = 0; mt < 4; mt++) {
                uint32_t off = (uint32_t)(((ks*16 + kq + li)*AP + mt*16 + mq) * 2);
                uint32_t ah[4], al[4];
                ldsm_x4t(ah[0], ah[1], ah[2], ah[3], bAh + off);
                ldsm_x4t(al[0], al[1], al[2], al[3], bAl + off);
                #pragma unroll
                for (int n4 = 0; n4 < 4; n4++) {
                    mma_bf16(acc[mt][n4], ah, wh[n4][ks][0], wh[n4][ks][1]);
                    mma_bf16(acc[mt][n4], ah, wl[n4][ks][0], wl[n4][ks][1]);
                    mma_bf16(acc[mt][n4], al, wh[n4][ks][0], wh[n4][ks][1]);
                }
            }
        }

        // ---- store partials (fp32) ----
        #pragma unroll
        for (int mt = 0; mt < 4; mt++) {
            int b0 = mt*16 + (lane >> 2);
            #pragma unroll
            for (int n4 = 0; n4 < 4; n4++) {
                int col = nt*128 + w*32 + n4*8 + (lane & 3)*2;
                *(float2*)&g_part[kc][(size_t)b0*HH + col] =
                    make_float2(acc[mt][n4][0], acc[mt][n4][1]);
                *(float2*)&g_part[kc][(size_t)(b0+8)*HH + col] =
                    make_float2(acc[mt][n4][2], acc[mt][n4][3]);
            }
        }

        // prefetch pre for B-role
        float4 pre4 = *(const float4*)&g_pre[(size_t)s*BH + o];

        grid_sync();    // all partials(s) visible

        // ---- B reduce + tanh + write h_s ----
        {
            float4 a4 = pre4;
            #pragma unroll
            for (int kk = 0; kk < KC; kk++) {
                float4 p = __ldcg((const float4*)&g_part[kk][o]);
                a4.x += p.x; a4.y += p.y; a4.z += p.z; a4.w += p.w;
            }
            float hv[4] = { tanh_fast(a4.x), tanh_fast(a4.y),
                            tanh_fast(a4.z), tanh_fast(a4.w) };
            #pragma unroll
            for (int j = 0; j < 4; j++) {
                __nv_bfloat16 hh = __float2bfloat16(hv[j]);
                g_hTh[s & 1][(oc+j)*BB + ob] = hh;
                g_hTl[s & 1][(oc+j)*BB + ob] =
                    __float2bfloat16(hv[j] - __bfloat162float(hh));
            }
            hlast = make_float4(hv[0], hv[1], hv[2], hv[3]);
            *(float4*)&out[(size_t)s*BH + o] = hlast;
        }

        grid_sync();    // h_s visible; guards partial-buffer WAR
    }

    *(float4*)&out[(size_t)SS*BH + o] = hlast;
}

// =================================================================================
// Launch
// =================================================================================
extern "C" void kernel_launch(void* const* d_in, const int* in_sizes, int n_in,
                              void* d_out, int out_size) {
    const float* x  = (const float*)d_in[0];   // (S,B,I)
    const float* Ww = (const float*)d_in[1];   // (H,H)
    const float* Wb = (const float*)d_in[2];   // (H)
    const float* Vw = (const float*)d_in[3];   // (H,I)
    const float* Vb = (const float*)d_in[4];   // (H)
    float* out = (float*)d_out;                // (S,B,H) then (1,B,H)

    static int attr_set = 0;
    const int rnn_smem = 2*128*AP*(int)sizeof(__nv_bfloat16);   // 36864
    if (!attr_set) {
        cudaFuncSetAttribute(rnn_recurrent_kernel,
                             cudaFuncAttributeMaxDynamicSharedMemorySize, rnn_smem);
        attr_set = 1;
    }

    // split-bf16 conversions
    __nv_bfloat16 *xhi, *xlo, *vhi, *vlo;
    cudaGetSymbolAddress((void**)&xhi, g_xhi);
    cudaGetSymbolAddress((void**)&xlo, g_xlo);
    cudaGetSymbolAddress((void**)&vhi, g_vhi);
    cudaGetSymbolAddress((void**)&vlo, g_vlo);
    convert_split_kernel<<<4096, 256>>>(x, xhi, xlo, SS*BB*II);
    convert_split_kernel<<<512, 256>>>(Vw, vhi, vlo, HH*II);

    // HMMA pre-GEMM
    dim3 gmma(256, 8);
    pre_hmma_kernel<<<gmma, 256>>>(Wb, Vb);

    // persistent recurrence (HMMA phase A)
    rnn_recurrent_kernel<<<NB, 128, rnn_smem>>>(Ww, out);
}

// round 17
// speedup vs baseline: 2.0643x; 1.1119x over previous
#include <cuda_runtime.h>
#include <cuda_bf16.h>
#include <math.h>
#include <cstdint>

// Problem dims
#define SS 512
#define BB 64
#define II 512
#define HH 1024
#define BH (BB*HH)

// Recurrent decomposition: 8 nt x 16 kc = 128 blocks
#define NT 8
#define KC 16
#define NB (NT*KC)
#define AP 72          // bf16 row pitch for staged A smem [b][k] (64 + 8 pad)

// -------------------- device scratch --------------------------------------------
__device__ float g_pre[SS*BH];              // Vx + biases; accumulates W.h via RED
__device__ unsigned g_bar_cnt = 0;
__device__ unsigned g_bar_gen = 0;
__device__ __nv_bfloat16 g_xhi[SS*BB*II];
__device__ __nv_bfloat16 g_xlo[SS*BB*II];
__device__ __nv_bfloat16 g_vhi[HH*II];
__device__ __nv_bfloat16 g_vlo[HH*II];

__device__ __forceinline__ float tanh_fast(float x) {
    float y; asm("tanh.approx.f32 %0, %1;" : "=f"(y) : "f"(x)); return y;
}

// -------------------- global ticket barrier (R13 release/acquire, proven) --------
__device__ __forceinline__ void grid_sync() {
    __syncthreads();
    if (threadIdx.x == 0) {
        unsigned gen;
        asm volatile("ld.relaxed.gpu.global.b32 %0, [%1];"
                     : "=r"(gen) : "l"(&g_bar_gen) : "memory");
        unsigned old;
        asm volatile("atom.acq_rel.gpu.global.add.u32 %0, [%1], %2;"
                     : "=r"(old) : "l"(&g_bar_cnt), "r"(1u) : "memory");
        if (old == NB - 1u) {
            asm volatile("st.relaxed.gpu.global.b32 [%0], %1;"
                         :: "l"(&g_bar_cnt), "r"(0u) : "memory");
            asm volatile("st.release.gpu.global.b32 [%0], %1;"
                         :: "l"(&g_bar_gen), "r"(gen + 1u) : "memory");
        } else {
            unsigned v;
            do {
                asm volatile("ld.acquire.gpu.global.b32 %0, [%1];"
                             : "=r"(v) : "l"(&g_bar_gen) : "memory");
            } while (v == gen);
        }
    }
    __syncthreads();
}

// -------------------- MMA helpers ------------------------------------------------
__device__ __forceinline__ void ldsm_x4(uint32_t& r0, uint32_t& r1,
                                        uint32_t& r2, uint32_t& r3, uint32_t a) {
    asm volatile("ldmatrix.sync.aligned.m8n8.x4.shared.b16 {%0,%1,%2,%3}, [%4];"
                 : "=r"(r0), "=r"(r1), "=r"(r2), "=r"(r3) : "r"(a));
}
__device__ __forceinline__ void ldsm_x2(uint32_t& r0, uint32_t& r1, uint32_t a) {
    asm volatile("ldmatrix.sync.aligned.m8n8.x2.shared.b16 {%0,%1}, [%2];"
                 : "=r"(r0), "=r"(r1) : "r"(a));
}
__device__ __forceinline__ void mma_bf16(float* c, const uint32_t* a,
                                         uint32_t b0, uint32_t b1) {
    asm volatile(
        "mma.sync.aligned.m16n8k16.row.col.f32.bf16.bf16.f32 "
        "{%0,%1,%2,%3}, {%4,%5,%6,%7}, {%8,%9}, {%0,%1,%2,%3};"
        : "+f"(c[0]), "+f"(c[1]), "+f"(c[2]), "+f"(c[3])
        : "r"(a[0]), "r"(a[1]), "r"(a[2]), "r"(a[3]), "r"(b0), "r"(b1));
}
__device__ __forceinline__ uint32_t smem_u32(const void* p) {
    uint32_t a;
    asm("{ .reg .u64 t; cvta.to.shared.u64 t, %1; cvt.u32.u64 %0, t; }"
        : "=r"(a) : "l"(p));
    return a;
}
__device__ __forceinline__ void red_add(float* p, float v) {
    asm volatile("red.relaxed.gpu.global.add.f32 [%0], %1;"
                 :: "l"(p), "f"(v) : "memory");
}

// =================================================================================
// Split-bf16 conversion: hi = bf16(v), lo = bf16(v - hi)
// =================================================================================
__global__ void convert_split_kernel(const float* __restrict__ src,
                                     __nv_bfloat16* __restrict__ hi,
                                     __nv_bfloat16* __restrict__ lo, int n) {
    for (int i = blockIdx.x*blockDim.x + threadIdx.x; i < n;
         i += gridDim.x*blockDim.x) {
        float v = src[i];
        __nv_bfloat16 h = __float2bfloat16(v);
        float r = v - __bfloat162float(h);
        hi[i] = h;
        lo[i] = __float2bfloat16(r);
    }
}

// =================================================================================
// HMMA pre-GEMM (R15 verbatim, proven): g_pre = x @ Vw^T + Vb + Wb
// =================================================================================
#define SROW 24

__global__ void __launch_bounds__(256, 2) pre_hmma_kernel(
        const float* __restrict__ Wb, const float* __restrict__ Vb) {
    __shared__ __nv_bfloat16 sAh[128*SROW];
    __shared__ __nv_bfloat16 sAl[128*SROW];
    __shared__ __nv_bfloat16 sBh[128*SROW];
    __shared__ __nv_bfloat16 sBl[128*SROW];

    const int bm = blockIdx.x;
    const int bn = blockIdx.y;
    const int t  = threadIdx.x;
    const int w  = t >> 5;
    const int lane = t & 31;
    const int wm = w & 3;
    const int wn = w >> 2;

    const int grow = t >> 1;
    const int gc8  = (t & 1) * 8;

    const __nv_bfloat16* Ah = g_xhi + (size_t)(bm*128 + grow)*II + gc8;
    const __nv_bfloat16* Al = g_xlo + (size_t)(bm*128 + grow)*II + gc8;
    const __nv_bfloat16* Bh = g_vhi + (size_t)(bn*128 + grow)*II + gc8;
    const __nv_bfloat16* Bl = g_vlo + (size_t)(bn*128 + grow)*II + gc8;

    __nv_bfloat16* dA_h = &sAh[grow*SROW + gc8];
    __nv_bfloat16* dA_l = &sAl[grow*SROW + gc8];
    __nv_bfloat16* dB_h = &sBh[grow*SROW + gc8];
    __nv_bfloat16* dB_l = &sBl[grow*SROW + gc8];

    const uint32_t baseAh = smem_u32(sAh);
    const uint32_t baseAl = smem_u32(sAl);
    const uint32_t baseBh = smem_u32(sBh);
    const uint32_t baseBl = smem_u32(sBl);
    const uint32_t aoff = (uint32_t)(((wm*32 + (lane & 15))*SROW + ((lane >> 4) & 1)*8) * 2);
    const uint32_t boff = (uint32_t)(((wn*64 + (lane & 7))*SROW + ((lane >> 3) & 1)*8) * 2);

    float acc[2][8][4];
    #pragma unroll
    for (int mf = 0; mf < 2; mf++)
        #pragma unroll
        for (int nf = 0; nf < 8; nf++)
            #pragma unroll
            for (int q = 0; q < 4; q++) acc[mf][nf][q] = 0.f;

    for (int kb = 0; kb < II/16; kb++) {
        uint4 va_h = *(const uint4*)(Ah + kb*16);
        uint4 va_l = *(const uint4*)(Al + kb*16);
        uint4 vb_h = *(const uint4*)(Bh + kb*16);
        uint4 vb_l = *(const uint4*)(Bl + kb*16);
        __syncthreads();
        *(uint4*)dA_h = va_h;
        *(uint4*)dA_l = va_l;
        *(uint4*)dB_h = vb_h;
        *(uint4*)dB_l = vb_l;
        __syncthreads();

        uint32_t ah[2][4], al[2][4];
        #pragma unroll
        for (int mf = 0; mf < 2; mf++) {
            uint32_t off = aoff + (uint32_t)(mf*16*SROW*2);
            ldsm_x4(ah[mf][0], ah[mf][1], ah[mf][2], ah[mf][3], baseAh + off);
            ldsm_x4(al[mf][0], al[mf][1], al[mf][2], al[mf][3], baseAl + off);
        }
        #pragma unroll
        for (int nf = 0; nf < 8; nf++) {
            uint32_t off = boff + (uint32_t)(nf*8*SROW*2);
            uint32_t bh0, bh1, bl0, bl1;
            ldsm_x2(bh0, bh1, baseBh + off);
            ldsm_x2(bl0, bl1, baseBl + off);
            #pragma unroll
            for (int mf = 0; mf < 2; mf++) {
                mma_bf16(acc[mf][nf], ah[mf], bh0, bh1);
                mma_bf16(acc[mf][nf], ah[mf], bl0, bl1);
                mma_bf16(acc[mf][nf], al[mf], bh0, bh1);
            }
        }
    }

    #pragma unroll
    for (int nf = 0; nf < 8; nf++) {
        int col = bn*128 + wn*64 + nf*8 + (lane & 3)*2;
        float b0 = Vb[col]   + Wb[col];
        float b1 = Vb[col+1] + Wb[col+1];
        #pragma unroll
        for (int mf = 0; mf < 2; mf++) {
            size_t row = (size_t)(bm*128 + wm*32 + mf*16 + (lane >> 2));
            float2 o0 = make_float2(acc[mf][nf][0] + b0, acc[mf][nf][1] + b1);
            float2 o1 = make_float2(acc[mf][nf][2] + b0, acc[mf][nf][3] + b1);
            *(float2*)&g_pre[row*HH + col]       = o0;
            *(float2*)&g_pre[(row+8)*HH + col]   = o1;
        }
    }
}

// =================================================================================
// Kernel 2: persistent recurrence — ONE barrier/step via RED-accumulate.
//   Block (nt,kc): stages h_{s-1} = tanh(g_pre[s-1][64b][kc*64:+64]) (fp32 ->
//   bf16 hi/lo, [b][k] natural layout), MMA 64b x 128n x 64k (W frags in regs),
//   red.add.f32 fragments into g_pre[s]. ONE grid barrier. nt==0 octet writes
//   out[s-1] from the staged tanh values. Final pass emits out[511] + h_final.
// =================================================================================
__global__ void __launch_bounds__(128) rnn_recurrent_kernel(
        const float* __restrict__ Ww,
        float* __restrict__ out) {
    extern __shared__ __nv_bfloat16 smb[];
    __nv_bfloat16* Ah = smb;               // [b=64][AP]  9216 B
    __nv_bfloat16* Al = smb + 64*AP;       // [b=64][AP]  9216 B
    // W conversion staging (startup only):
    __nv_bfloat16* Whs = smb;              // [n=128][AP] 18432 B
    __nv_bfloat16* Wls = smb + 128*AP;     // [n=128][AP] 18432 B

    const int bid = blockIdx.x;
    const int nt  = bid & (NT-1);
    const int kc  = bid >> 3;
    const int t   = threadIdx.x;
    const int w   = t >> 5;               // warp: n cols [w*32, +32)
    const int lane = t & 31;

    // ---- startup: convert Ww slice to split-bf16, load fragments to regs ----
    for (int q = t; q < 128*64; q += 128) {
        int n = q >> 6, k = q & 63;
        float v = Ww[(size_t)(nt*128 + n)*HH + kc*64 + k];
        __nv_bfloat16 h = __float2bfloat16(v);
        Whs[n*AP + k] = h;
        Wls[n*AP + k] = __float2bfloat16(v - __bfloat162float(h));
    }
    __syncthreads();

    uint32_t wh[4][4][2], wl[4][4][2];     // [ntile][kstep][2 regs]
    {
        const uint32_t bWh = smem_u32(Whs);
        const uint32_t bWl = smem_u32(Wls);
        const int i  = lane & 7;
        const int sel = (lane >> 3) & 1;
        #pragma unroll
        for (int n4 = 0; n4 < 4; n4++)
            #pragma unroll
            for (int ks = 0; ks < 4; ks++) {
                uint32_t off = (uint32_t)(((w*32 + n4*8 + i)*AP + ks*16 + sel*8) * 2);
                ldsm_x2(wh[n4][ks][0], wh[n4][ks][1], bWh + off);
                ldsm_x2(wl[n4][ks][0], wl[n4][ks][1], bWl + off);
            }
    }
    __syncthreads();   // W smem dead; reuse as Ah/Al

    const uint32_t bAh = smem_u32(Ah);
    const uint32_t bAl = smem_u32(Al);
    const uint32_t aoffb = (uint32_t)(((lane & 15)*AP + ((lane >> 4) & 1)*8) * 2);

    for (int s = 1; s < SS; s++) {
        // ---- stage: read g_pre[s-1] slice, tanh, split, [b][k] layout ----
        {
            const float* src = g_pre + (size_t)(s-1)*BH + kc*64;
            float* dsto = out + (size_t)(s-1)*BH + kc*64;
            #pragma unroll
            for (int j = 0; j < 8; j++) {
                int idx = t + j*128;          // 0..1023 float4 units (64b x 16)
                int b   = idx >> 4;
                int k4  = (idx & 15) << 2;
                float4 p = __ldcg((const float4*)(src + (size_t)b*HH + k4));
                float h0 = tanh_fast(p.x), h1 = tanh_fast(p.y);
                float h2 = tanh_fast(p.z), h3 = tanh_fast(p.w);
                if (nt == 0)
                    *(float4*)(dsto + (size_t)b*HH + k4) = make_float4(h0, h1, h2, h3);
                __nv_bfloat16 hh0 = __float2bfloat16(h0);
                __nv_bfloat16 hh1 = __float2bfloat16(h1);
                __nv_bfloat16 hh2 = __float2bfloat16(h2);
                __nv_bfloat16 hh3 = __float2bfloat16(h3);
                __nv_bfloat162 ph0; ph0.x = hh0; ph0.y = hh1;
                __nv_bfloat162 ph1; ph1.x = hh2; ph1.y = hh3;
                *(__nv_bfloat162*)&Ah[b*AP + k4]     = ph0;
                *(__nv_bfloat162*)&Ah[b*AP + k4 + 2] = ph1;
                __nv_bfloat162 pl0, pl1;
                pl0.x = __float2bfloat16(h0 - __bfloat162float(hh0));
                pl0.y = __float2bfloat16(h1 - __bfloat162float(hh1));
                pl1.x = __float2bfloat16(h2 - __bfloat162float(hh2));
                pl1.y = __float2bfloat16(h3 - __bfloat162float(hh3));
                *(__nv_bfloat162*)&Al[b*AP + k4]     = pl0;
                *(__nv_bfloat162*)&Al[b*AP + k4 + 2] = pl1;
            }
        }
        __syncthreads();

        // ---- MMA: m=64 (4 tiles) x n=32/warp (4 tiles) x k=64 (4 steps) ----
        float acc[4][4][4];
        #pragma unroll
        for (int mt = 0; mt < 4; mt++)
            #pragma unroll
            for (int n4 = 0; n4 < 4; n4++)
                #pragma unroll
                for (int q = 0; q < 4; q++) acc[mt][n4][q] = 0.f;

        #pragma unroll
        for (int ks = 0; ks < 4; ks++) {
            #pragma unroll
            for (int mt = 0; mt < 4; mt++) {
                uint32_t off = aoffb + (uint32_t)((mt*16*AP + ks*16) * 2);
                uint32_t ah[4], al[4];
                ldsm_x4(ah[0], ah[1], ah[2], ah[3], bAh + off);
                ldsm_x4(al[0], al[1], al[2], al[3], bAl + off);
                #pragma unroll
                for (int n4 = 0; n4 < 4; n4++) {
                    mma_bf16(acc[mt][n4], ah, wh[n4][ks][0], wh[n4][ks][1]);
                    mma_bf16(acc[mt][n4], ah, wl[n4][ks][0], wl[n4][ks][1]);
                    mma_bf16(acc[mt][n4], al, wh[n4][ks][0], wh[n4][ks][1]);
                }
            }
        }
        __syncthreads();   // Ah/Al fully consumed before next step overwrite

        // ---- RED-accumulate fragments into g_pre[s] ----
        {
            float* dst = g_pre + (size_t)s*BH;
            #pragma unroll
            for (int mt = 0; mt < 4; mt++) {
                int b0 = mt*16 + (lane >> 2);
                #pragma unroll
                for (int n4 = 0; n4 < 4; n4++) {
                    int col = nt*128 + w*32 + n4*8 + (lane & 3)*2;
                    float* p0 = dst + (size_t)b0*HH + col;
                    float* p1 = dst + (size_t)(b0+8)*HH + col;
                    red_add(p0,     acc[mt][n4][0]);
                    red_add(p0 + 1, acc[mt][n4][1]);
                    red_add(p1,     acc[mt][n4][2]);
                    red_add(p1 + 1, acc[mt][n4][3]);
                }
            }
        }

        grid_sync();    // g_pre[s] complete grid-wide
    }

    // ---- final: out[511] = tanh(g_pre[511]); h_final duplicate ----
    if (nt == 0) {
        const float* src = g_pre + (size_t)511*BH + kc*64;
        float* d0 = out + (size_t)511*BH + kc*64;
        float* d1 = out + (size_t)512*BH + kc*64;
        #pragma unroll
        for (int j = 0; j < 8; j++) {
            int idx = t + j*128;
            int b   = idx >> 4;
            int k4  = (idx & 15) << 2;
            float4 p = __ldcg((const float4*)(src + (size_t)b*HH + k4));
            float4 h = make_float4(tanh_fast(p.x), tanh_fast(p.y),
                                   tanh_fast(p.z), tanh_fast(p.w));
            *(float4*)(d0 + (size_t)b*HH + k4) = h;
            *(float4*)(d1 + (size_t)b*HH + k4) = h;
        }
    }
}

// =================================================================================
// Launch
// =================================================================================
extern "C" void kernel_launch(void* const* d_in, const int* in_sizes, int n_in,
                              void* d_out, int out_size) {
    const float* x  = (const float*)d_in[0];   // (S,B,I)
    const float* Ww = (const float*)d_in[1];   // (H,H)
    const float* Wb = (const float*)d_in[2];   // (H)
    const float* Vw = (const float*)d_in[3];   // (H,I)
    const float* Vb = (const float*)d_in[4];   // (H)
    float* out = (float*)d_out;                // (S,B,H) then (1,B,H)

    static int attr_set = 0;
    const int rnn_smem = 2*128*AP*(int)sizeof(__nv_bfloat16);   // 36864
    if (!attr_set) {
        cudaFuncSetAttribute(rnn_recurrent_kernel,
                             cudaFuncAttributeMaxDynamicSharedMemorySize, rnn_smem);
        attr_set = 1;
    }

    // split-bf16 conversions
    __nv_bfloat16 *xhi, *xlo, *vhi, *vlo;
    cudaGetSymbolAddress((void**)&xhi, g_xhi);
    cudaGetSymbolAddress((void**)&xlo, g_xlo);
    cudaGetSymbolAddress((void**)&vhi, g_vhi);
    cudaGetSymbolAddress((void**)&vlo, g_vlo);
    convert_split_kernel<<<4096, 256>>>(x, xhi, xlo, SS*BB*II);
    convert_split_kernel<<<512, 256>>>(Vw, vhi, vlo, HH*II);

    // HMMA pre-GEMM (writes fresh g_pre every launch -> replay-safe accumulation)
    dim3 gmma(256, 8);
    pre_hmma_kernel<<<gmma, 256>>>(Wb, Vb);

    // persistent recurrence (RED-accumulate, one barrier/step)
    rnn_recurrent_kernel<<<NB, 128, rnn_smem>>>(Ww, out);
}